// round 1
// baseline (speedup 1.0000x reference)
#include <cuda_runtime.h>
#include <cuda_bf16.h>
#include <cstddef>

// Problem constants
#define B_   64
#define S_   128
#define Wc_  16
#define E_   256
#define H_   512
#define NC_  20
#define NW_  (B_*S_)        // 8192 words total
#define G_   (4*H_)         // 2048 word-LSTM gate width
#define CH_  (2*H_)         // 1024 char-LSTM hidden
#define CG_  (4*CH_)        // 4096 char-LSTM gate width

// ---------------- scratch (static device globals; no allocation) ----------------
__device__ float g_Xemb[(size_t)NW_*E_];     // word embeddings     [8192,256]
__device__ float g_XGf [(size_t)NW_*G_];     // fwd x-gates         [8192,2048]
__device__ float g_XGb [(size_t)NW_*G_];     // bwd x-gates         [8192,2048]
__device__ float g_H0  [(size_t)NW_*CH_];    // layer0 output       [8192,1024]
__device__ float g_H1  [(size_t)NW_*CH_];    // layer1 output       [8192,1024]
__device__ float g_hf[B_*H_], g_cf[B_*H_];   // fwd state
__device__ float g_hb[B_*H_], g_cb[B_*H_];   // bwd state
__device__ float g_Zf[B_*G_], g_Zb[B_*G_];   // per-step recurrent gates
__device__ float g_P  [(size_t)128*CG_];     // char_emb @ c_Wih.T  [128,4096]
__device__ float g_Zc [(size_t)NW_*CG_];     // char recurrent gates[8192,4096]
__device__ float g_ch [(size_t)NW_*CH_];     // char h state/final  [8192,1024]
__device__ float g_cc [(size_t)NW_*CH_];     // char c state        [8192,1024]

__device__ __forceinline__ float sigf(float x) { return 1.f / (1.f + __expf(-x)); }

// ---------------- SGEMM: C[M,N] = A[M,K] @ B[N,K]^T (+bias[n]) ----------------
// 128x128 tile, 256 threads, 8x8 microtile, K-chunk 8, reg-prefetch double buffer.
// Requires M%128==0, N%128==0, K%8==0, all pointers 16B-aligned.
__global__ __launch_bounds__(256)
void sgemm128(const float* __restrict__ A, const float* __restrict__ Bm,
              float* __restrict__ C, const float* __restrict__ bias,
              int M, int N, int K)
{
    __shared__ float As[8][128];
    __shared__ float Bs[8][128];
    const int tid = threadIdx.x;
    const int tx  = tid & 15;
    const int ty  = tid >> 4;
    const int row0 = blockIdx.y * 128;
    const int col0 = blockIdx.x * 128;
    const int lr = tid >> 1;          // 0..127
    const int lk = (tid & 1) * 4;     // 0 or 4

    const float* Ap = A  + (size_t)(row0 + lr) * K + lk;
    const float* Bp = Bm + (size_t)(col0 + lr) * K + lk;

    float acc[8][8];
#pragma unroll
    for (int i = 0; i < 8; ++i)
#pragma unroll
        for (int j = 0; j < 8; ++j) acc[i][j] = 0.f;

    {
        float4 a = *(const float4*)Ap;
        float4 b = *(const float4*)Bp;
        As[lk+0][lr] = a.x; As[lk+1][lr] = a.y; As[lk+2][lr] = a.z; As[lk+3][lr] = a.w;
        Bs[lk+0][lr] = b.x; Bs[lk+1][lr] = b.y; Bs[lk+2][lr] = b.z; Bs[lk+3][lr] = b.w;
    }
    __syncthreads();

    int k0 = 0;
    while (true) {
        const int kn = k0 + 8;
        const bool more = kn < K;
        float4 an, bn;
        if (more) { an = *(const float4*)(Ap + kn); bn = *(const float4*)(Bp + kn); }
#pragma unroll
        for (int k = 0; k < 8; ++k) {
            float4 a0 = *(const float4*)&As[k][ty*8];
            float4 a1 = *(const float4*)&As[k][ty*8+4];
            float4 b0 = *(const float4*)&Bs[k][tx*8];
            float4 b1 = *(const float4*)&Bs[k][tx*8+4];
            float av[8] = {a0.x,a0.y,a0.z,a0.w,a1.x,a1.y,a1.z,a1.w};
            float bv[8] = {b0.x,b0.y,b0.z,b0.w,b1.x,b1.y,b1.z,b1.w};
#pragma unroll
            for (int i = 0; i < 8; ++i)
#pragma unroll
                for (int j = 0; j < 8; ++j)
                    acc[i][j] = fmaf(av[i], bv[j], acc[i][j]);
        }
        if (!more) break;
        __syncthreads();
        As[lk+0][lr] = an.x; As[lk+1][lr] = an.y; As[lk+2][lr] = an.z; As[lk+3][lr] = an.w;
        Bs[lk+0][lr] = bn.x; Bs[lk+1][lr] = bn.y; Bs[lk+2][lr] = bn.z; Bs[lk+3][lr] = bn.w;
        __syncthreads();
        k0 = kn;
    }

    float bv0[8];
#pragma unroll
    for (int j = 0; j < 8; ++j) bv0[j] = bias ? bias[col0 + tx*8 + j] : 0.f;
#pragma unroll
    for (int i = 0; i < 8; ++i) {
        const int r = row0 + ty*8 + i;
        float4 o0, o1;
        o0.x = acc[i][0]+bv0[0]; o0.y = acc[i][1]+bv0[1];
        o0.z = acc[i][2]+bv0[2]; o0.w = acc[i][3]+bv0[3];
        o1.x = acc[i][4]+bv0[4]; o1.y = acc[i][5]+bv0[5];
        o1.z = acc[i][6]+bv0[6]; o1.w = acc[i][7]+bv0[7];
        *(float4*)(C + (size_t)r*N + col0 + tx*8)     = o0;
        *(float4*)(C + (size_t)r*N + col0 + tx*8 + 4) = o1;
    }
}

// ---------------- dual small GEMM for word recurrence (fwd+bwd in one launch) --
// 64x64 tile, 256 threads, 4x4 microtile, K-chunk 16. blockIdx.z selects pair.
__global__ __launch_bounds__(256)
void sgemm64_dual(const float* __restrict__ A0, const float* __restrict__ B0, float* __restrict__ C0,
                  const float* __restrict__ A1, const float* __restrict__ B1, float* __restrict__ C1,
                  int M, int N, int K)
{
    const float* A  = blockIdx.z ? A1 : A0;
    const float* Bm = blockIdx.z ? B1 : B0;
    float*       C  = blockIdx.z ? C1 : C0;
    __shared__ float As[16][64];
    __shared__ float Bs[16][64];
    const int tid = threadIdx.x;
    const int tx = tid & 15, ty = tid >> 4;
    const int row0 = blockIdx.y * 64, col0 = blockIdx.x * 64;
    const int lr = tid >> 2;          // 0..63
    const int lk = (tid & 3) * 4;     // 0,4,8,12

    const float* Ap = A  + (size_t)(row0 + lr) * K + lk;
    const float* Bp = Bm + (size_t)(col0 + lr) * K + lk;

    float acc[4][4];
#pragma unroll
    for (int i = 0; i < 4; ++i)
#pragma unroll
        for (int j = 0; j < 4; ++j) acc[i][j] = 0.f;

    {
        float4 a = *(const float4*)Ap;
        float4 b = *(const float4*)Bp;
        As[lk+0][lr] = a.x; As[lk+1][lr] = a.y; As[lk+2][lr] = a.z; As[lk+3][lr] = a.w;
        Bs[lk+0][lr] = b.x; Bs[lk+1][lr] = b.y; Bs[lk+2][lr] = b.z; Bs[lk+3][lr] = b.w;
    }
    __syncthreads();

    int k0 = 0;
    while (true) {
        const int kn = k0 + 16;
        const bool more = kn < K;
        float4 an, bn;
        if (more) { an = *(const float4*)(Ap + kn); bn = *(const float4*)(Bp + kn); }
#pragma unroll
        for (int k = 0; k < 16; ++k) {
            float4 a4 = *(const float4*)&As[k][ty*4];
            float4 b4 = *(const float4*)&Bs[k][tx*4];
            float aa[4] = {a4.x,a4.y,a4.z,a4.w};
            float bb[4] = {b4.x,b4.y,b4.z,b4.w};
#pragma unroll
            for (int i = 0; i < 4; ++i)
#pragma unroll
                for (int j = 0; j < 4; ++j)
                    acc[i][j] = fmaf(aa[i], bb[j], acc[i][j]);
        }
        if (!more) break;
        __syncthreads();
        As[lk+0][lr] = an.x; As[lk+1][lr] = an.y; As[lk+2][lr] = an.z; As[lk+3][lr] = an.w;
        Bs[lk+0][lr] = bn.x; Bs[lk+1][lr] = bn.y; Bs[lk+2][lr] = bn.z; Bs[lk+3][lr] = bn.w;
        __syncthreads();
        k0 = kn;
    }

#pragma unroll
    for (int i = 0; i < 4; ++i) {
        const int r = row0 + ty*4 + i;
        float4 o;
        o.x = acc[i][0]; o.y = acc[i][1]; o.z = acc[i][2]; o.w = acc[i][3];
        *(float4*)(C + (size_t)r*N + col0 + tx*4) = o;
    }
}

// ---------------- word embedding gather ----------------
__global__ void embed_words(const int* __restrict__ words, const float* __restrict__ emb)
{
    const int m = blockIdx.x;
    const int e = threadIdx.x;
    g_Xemb[(size_t)m*E_ + e] = emb[(size_t)words[m]*E_ + e];
}

// ---------------- word LSTM gate step (fwd dir=z0, bwd dir=z1) ----------------
// fwd: z = Zf + XGf[row t]; write masked h to Hout[:, 0:512]
// bwd: gather x at src=len-1-t, scatter h to Hout[src, 512:1024] (rev_pad identity)
__global__ void word_gate(const float* __restrict__ XGf, const float* __restrict__ XGb,
                          const int* __restrict__ lens, float* __restrict__ Hout, int t)
{
    const int j = blockIdx.x * blockDim.x + threadIdx.x;   // 0..511
    const int b = blockIdx.y;
    const int len = lens[b];
    const bool valid = t < len;
    if (blockIdx.z == 0) {
        const float* Z  = g_Zf + b * G_;
        const float* xg = XGf + (size_t)(b * S_ + t) * G_;
        float zi = Z[j]        + xg[j];
        float zf = Z[H_+j]     + xg[H_+j];
        float zg = Z[2*H_+j]   + xg[2*H_+j];
        float zo = Z[3*H_+j]   + xg[3*H_+j];
        float c  = g_cf[b*H_+j];
        float cn = sigf(zf)*c + sigf(zi)*tanhf(zg);
        float hn = sigf(zo)*tanhf(cn);
        if (valid) { g_cf[b*H_+j] = cn; g_hf[b*H_+j] = hn; }
        Hout[(size_t)(b*S_+t)*CH_ + j] = valid ? hn : 0.f;
    } else {
        const int src = valid ? (len - 1 - t) : t;
        const float* Z  = g_Zb + b * G_;
        const float* xg = XGb + (size_t)(b * S_ + src) * G_;
        float zi = Z[j]        + xg[j];
        float zf = Z[H_+j]     + xg[H_+j];
        float zg = Z[2*H_+j]   + xg[2*H_+j];
        float zo = Z[3*H_+j]   + xg[3*H_+j];
        float c  = g_cb[b*H_+j];
        float cn = sigf(zf)*c + sigf(zi)*tanhf(zg);
        float hn = sigf(zo)*tanhf(cn);
        if (valid) {
            g_cb[b*H_+j] = cn; g_hb[b*H_+j] = hn;
            Hout[(size_t)(b*S_+src)*CH_ + H_ + j] = hn;  // scatter == rev_pad output
        }
    }
}

// ---------------- char LSTM gate step ----------------
// x-gates come from the 128-row precomputed table P (gather by token id).
__global__ void char_gate(const int* __restrict__ chars, const int* __restrict__ clens,
                          const float* __restrict__ cbias, int t, int useZ)
{
    const int n = blockIdx.y;
    if (t >= clens[n]) return;                 // frozen row: skip (whole block uniform)
    const int j = blockIdx.x * blockDim.x + threadIdx.x;   // 0..1023
    const int tok = chars[n * Wc_ + t];
    const float* p = g_P + (size_t)tok * CG_;
    float zi = p[j]        + cbias[j];
    float zf = p[CH_+j]    + cbias[CH_+j];
    float zg = p[2*CH_+j]  + cbias[2*CH_+j];
    float zo = p[3*CH_+j]  + cbias[3*CH_+j];
    if (useZ) {
        const float* Z = g_Zc + (size_t)n * CG_;
        zi += Z[j]; zf += Z[CH_+j]; zg += Z[2*CH_+j]; zo += Z[3*CH_+j];
    }
    float c  = g_cc[(size_t)n*CH_+j];
    float cn = sigf(zf)*c + sigf(zi)*tanhf(zg);
    float hn = sigf(zo)*tanhf(cn);
    g_cc[(size_t)n*CH_+j] = cn;
    g_ch[(size_t)n*CH_+j] = hn;
}

// ---------------- final head: out = (Hword + valid*Hchar) @ lin_W.T + lin_b ----
__global__ __launch_bounds__(256)
void final_linear(const int* __restrict__ wnum, const float* __restrict__ W,
                  const float* __restrict__ bias, float* __restrict__ out)
{
    const int row = blockIdx.x;         // 0..8191
    const int b = row >> 7;
    const int s = row & (S_ - 1);
    const bool valid = s < wnum[b];
    __shared__ float v[CH_];
    __shared__ float sred[8*NC_];
    const int tid = threadIdx.x;
    for (int j = tid; j < CH_; j += 256) {
        float x = g_H1[(size_t)row*CH_ + j];
        if (valid) x += g_ch[(size_t)row*CH_ + j];
        v[j] = x;
    }
    __syncthreads();
    float acc[NC_];
#pragma unroll
    for (int c2 = 0; c2 < NC_; ++c2) acc[c2] = 0.f;
    for (int j = tid; j < CH_; j += 256) {
        float x = v[j];
#pragma unroll
        for (int c2 = 0; c2 < NC_; ++c2)
            acc[c2] = fmaf(x, W[c2*CH_ + j], acc[c2]);
    }
#pragma unroll
    for (int c2 = 0; c2 < NC_; ++c2)
#pragma unroll
        for (int off = 16; off > 0; off >>= 1)
            acc[c2] += __shfl_down_sync(0xffffffffu, acc[c2], off);
    const int lane = tid & 31, w = tid >> 5;
    if (lane == 0)
#pragma unroll
        for (int c2 = 0; c2 < NC_; ++c2) sred[w*NC_ + c2] = acc[c2];
    __syncthreads();
    if (tid < NC_) {
        float sum = bias[tid];
#pragma unroll
        for (int w2 = 0; w2 < 8; ++w2) sum += sred[w2*NC_ + tid];
        out[(size_t)row*NC_ + tid] = sum;
    }
}

// ================================================================================
extern "C" void kernel_launch(void* const* d_in, const int* in_sizes, int n_in,
                              void* d_out, int out_size)
{
    (void)in_sizes; (void)n_in; (void)out_size;
    const int*   words     = (const int*)  d_in[0];
    const int*   words_num = (const int*)  d_in[1];
    const int*   chars     = (const int*)  d_in[2];
    const int*   char_lens = (const int*)  d_in[3];
    const float* word_emb  = (const float*)d_in[4];
    const float* char_emb  = (const float*)d_in[5];
    const float* l0_Wih    = (const float*)d_in[6];
    const float* l0_Whh    = (const float*)d_in[7];
    const float* l0_b      = (const float*)d_in[8];
    const float* l1_Wih    = (const float*)d_in[9];
    const float* l1_Whh    = (const float*)d_in[10];
    const float* l1_b      = (const float*)d_in[11];
    const float* c_Wih     = (const float*)d_in[12];
    const float* c_Whh     = (const float*)d_in[13];
    const float* c_b       = (const float*)d_in[14];
    const float* lin_W     = (const float*)d_in[15];
    const float* lin_b     = (const float*)d_in[16];
    float* out = (float*)d_out;

    float *Xemb, *XGf, *XGb, *H0, *H1, *hf, *cf, *hb, *cb, *Zf, *Zb, *P, *Zc, *ch, *cc;
    cudaGetSymbolAddress((void**)&Xemb, g_Xemb);
    cudaGetSymbolAddress((void**)&XGf,  g_XGf);
    cudaGetSymbolAddress((void**)&XGb,  g_XGb);
    cudaGetSymbolAddress((void**)&H0,   g_H0);
    cudaGetSymbolAddress((void**)&H1,   g_H1);
    cudaGetSymbolAddress((void**)&hf,   g_hf);
    cudaGetSymbolAddress((void**)&cf,   g_cf);
    cudaGetSymbolAddress((void**)&hb,   g_hb);
    cudaGetSymbolAddress((void**)&cb,   g_cb);
    cudaGetSymbolAddress((void**)&Zf,   g_Zf);
    cudaGetSymbolAddress((void**)&Zb,   g_Zb);
    cudaGetSymbolAddress((void**)&P,    g_P);
    cudaGetSymbolAddress((void**)&Zc,   g_Zc);
    cudaGetSymbolAddress((void**)&ch,   g_ch);
    cudaGetSymbolAddress((void**)&cc,   g_cc);

    // ---- word embeddings ----
    embed_words<<<NW_, E_>>>(words, word_emb);

    // ---- word BiLSTM layer 0 (input: Xemb, K=256) ----
    {
        const float* Wih0 = l0_Wih;
        const float* Wih1 = l0_Wih + (size_t)G_ * E_;
        const float* Whh0 = l0_Whh;
        const float* Whh1 = l0_Whh + (size_t)G_ * H_;
        sgemm128<<<dim3(G_/128, NW_/128), 256>>>(Xemb, Wih0, XGf, l0_b,      NW_, G_, E_);
        sgemm128<<<dim3(G_/128, NW_/128), 256>>>(Xemb, Wih1, XGb, l0_b + G_, NW_, G_, E_);
        cudaMemsetAsync(H0, 0, (size_t)NW_*CH_*sizeof(float), 0);
        cudaMemsetAsync(hf, 0, B_*H_*sizeof(float), 0);
        cudaMemsetAsync(cf, 0, B_*H_*sizeof(float), 0);
        cudaMemsetAsync(hb, 0, B_*H_*sizeof(float), 0);
        cudaMemsetAsync(cb, 0, B_*H_*sizeof(float), 0);
        for (int t = 0; t < S_; ++t) {
            sgemm64_dual<<<dim3(G_/64, 1, 2), 256>>>(hf, Whh0, Zf, hb, Whh1, Zb, B_, G_, H_);
            word_gate<<<dim3(H_/256, B_, 2), 256>>>(XGf, XGb, words_num, H0, t);
        }
    }

    // ---- word BiLSTM layer 1 (input: H0, K=1024) ----
    {
        const float* Wih0 = l1_Wih;
        const float* Wih1 = l1_Wih + (size_t)G_ * CH_;
        const float* Whh0 = l1_Whh;
        const float* Whh1 = l1_Whh + (size_t)G_ * H_;
        sgemm128<<<dim3(G_/128, NW_/128), 256>>>(H0, Wih0, XGf, l1_b,      NW_, G_, CH_);
        sgemm128<<<dim3(G_/128, NW_/128), 256>>>(H0, Wih1, XGb, l1_b + G_, NW_, G_, CH_);
        cudaMemsetAsync(H1, 0, (size_t)NW_*CH_*sizeof(float), 0);
        cudaMemsetAsync(hf, 0, B_*H_*sizeof(float), 0);
        cudaMemsetAsync(cf, 0, B_*H_*sizeof(float), 0);
        cudaMemsetAsync(hb, 0, B_*H_*sizeof(float), 0);
        cudaMemsetAsync(cb, 0, B_*H_*sizeof(float), 0);
        for (int t = 0; t < S_; ++t) {
            sgemm64_dual<<<dim3(G_/64, 1, 2), 256>>>(hf, Whh0, Zf, hb, Whh1, Zb, B_, G_, H_);
            word_gate<<<dim3(H_/256, B_, 2), 256>>>(XGf, XGb, words_num, H1, t);
        }
    }

    // ---- char LSTM over 8192 sequences of length 16 ----
    // x-projection collapses to a 128-row table: P = char_emb @ c_Wih.T
    sgemm128<<<dim3(CG_/128, 1), 256>>>(char_emb, c_Wih, P, nullptr, 128, CG_, E_);
    cudaMemsetAsync(ch, 0, (size_t)NW_*CH_*sizeof(float), 0);
    cudaMemsetAsync(cc, 0, (size_t)NW_*CH_*sizeof(float), 0);
    for (int t = 0; t < Wc_; ++t) {
        if (t > 0)
            sgemm128<<<dim3(CG_/128, NW_/128), 256>>>(ch, c_Whh, Zc, nullptr, NW_, CG_, CH_);
        char_gate<<<dim3(CH_/256, NW_), 256>>>(chars, char_lens, c_b, t, t > 0);
    }

    // ---- head ----
    final_linear<<<NW_, 256>>>(words_num, lin_W, lin_b, out);
}

// round 2
// speedup vs baseline: 1.0552x; 1.0552x over previous
#include <cuda_runtime.h>
#include <cuda_bf16.h>
#include <cstddef>

// Problem constants
#define B_   64
#define S_   128
#define Wc_  16
#define E_   256
#define H_   512
#define NC_  20
#define NW_  (B_*S_)        // 8192 words total
#define G_   (4*H_)         // 2048 word-LSTM gate width
#define CH_  (2*H_)         // 1024 char-LSTM hidden
#define CG_  (4*CH_)        // 4096 char-LSTM gate width

#define NBLK_ 128           // persistent word-layer blocks (2 dirs x 64 j-tiles)

// ---------------- scratch (static device globals; no allocation) ----------------
__device__ float g_Xemb[(size_t)NW_*E_];     // word embeddings     [8192,256]
__device__ float g_XGf [(size_t)NW_*G_];     // fwd x-gates         [8192,2048]
__device__ float g_XGb [(size_t)NW_*G_];     // bwd x-gates         [8192,2048]
__device__ float g_H0  [(size_t)NW_*CH_];    // layer0 output       [8192,1024]
__device__ float g_H1  [(size_t)NW_*CH_];    // layer1 output       [8192,1024]
__device__ float g_hpp[(size_t)2*2*B_*H_];   // h ping-pong [buf][dir][64,512]
__device__ unsigned g_bar;                   // grid barrier counter
__device__ float g_P  [(size_t)128*CG_];     // char_emb @ c_Wih.T  [128,4096]
__device__ float g_Zc [(size_t)NW_*CG_];     // char recurrent gates[8192,4096]
__device__ float g_ch [(size_t)NW_*CH_];     // char h state/final  [8192,1024]
__device__ float g_cc [(size_t)NW_*CH_];     // char c state        [8192,1024]

__device__ __forceinline__ float sigf(float x) { return 1.f / (1.f + __expf(-x)); }

// ---------------- SGEMM: C[M,N] = A[M,K] @ B[N,K]^T (+bias[n]) ----------------
// 128x128 tile, 256 threads, 8x8 microtile, K-chunk 8, reg-prefetch double buffer.
__global__ __launch_bounds__(256)
void sgemm128(const float* __restrict__ A, const float* __restrict__ Bm,
              float* __restrict__ C, const float* __restrict__ bias,
              int M, int N, int K)
{
    __shared__ float As[8][128];
    __shared__ float Bs[8][128];
    const int tid = threadIdx.x;
    const int tx  = tid & 15;
    const int ty  = tid >> 4;
    const int row0 = blockIdx.y * 128;
    const int col0 = blockIdx.x * 128;
    const int lr = tid >> 1;
    const int lk = (tid & 1) * 4;

    const float* Ap = A  + (size_t)(row0 + lr) * K + lk;
    const float* Bp = Bm + (size_t)(col0 + lr) * K + lk;

    float acc[8][8];
#pragma unroll
    for (int i = 0; i < 8; ++i)
#pragma unroll
        for (int j = 0; j < 8; ++j) acc[i][j] = 0.f;

    {
        float4 a = *(const float4*)Ap;
        float4 b = *(const float4*)Bp;
        As[lk+0][lr] = a.x; As[lk+1][lr] = a.y; As[lk+2][lr] = a.z; As[lk+3][lr] = a.w;
        Bs[lk+0][lr] = b.x; Bs[lk+1][lr] = b.y; Bs[lk+2][lr] = b.z; Bs[lk+3][lr] = b.w;
    }
    __syncthreads();

    int k0 = 0;
    while (true) {
        const int kn = k0 + 8;
        const bool more = kn < K;
        float4 an, bn;
        if (more) { an = *(const float4*)(Ap + kn); bn = *(const float4*)(Bp + kn); }
#pragma unroll
        for (int k = 0; k < 8; ++k) {
            float4 a0 = *(const float4*)&As[k][ty*8];
            float4 a1 = *(const float4*)&As[k][ty*8+4];
            float4 b0 = *(const float4*)&Bs[k][tx*8];
            float4 b1 = *(const float4*)&Bs[k][tx*8+4];
            float av[8] = {a0.x,a0.y,a0.z,a0.w,a1.x,a1.y,a1.z,a1.w};
            float bv[8] = {b0.x,b0.y,b0.z,b0.w,b1.x,b1.y,b1.z,b1.w};
#pragma unroll
            for (int i = 0; i < 8; ++i)
#pragma unroll
                for (int j = 0; j < 8; ++j)
                    acc[i][j] = fmaf(av[i], bv[j], acc[i][j]);
        }
        if (!more) break;
        __syncthreads();
        As[lk+0][lr] = an.x; As[lk+1][lr] = an.y; As[lk+2][lr] = an.z; As[lk+3][lr] = an.w;
        Bs[lk+0][lr] = bn.x; Bs[lk+1][lr] = bn.y; Bs[lk+2][lr] = bn.z; Bs[lk+3][lr] = bn.w;
        __syncthreads();
        k0 = kn;
    }

    float bv0[8];
#pragma unroll
    for (int j = 0; j < 8; ++j) bv0[j] = bias ? bias[col0 + tx*8 + j] : 0.f;
#pragma unroll
    for (int i = 0; i < 8; ++i) {
        const int r = row0 + ty*8 + i;
        float4 o0, o1;
        o0.x = acc[i][0]+bv0[0]; o0.y = acc[i][1]+bv0[1];
        o0.z = acc[i][2]+bv0[2]; o0.w = acc[i][3]+bv0[3];
        o1.x = acc[i][4]+bv0[4]; o1.y = acc[i][5]+bv0[5];
        o1.z = acc[i][6]+bv0[6]; o1.w = acc[i][7]+bv0[7];
        *(float4*)(C + (size_t)r*N + col0 + tx*8)     = o0;
        *(float4*)(C + (size_t)r*N + col0 + tx*8 + 4) = o1;
    }
}

// ---------------- persistent word BiLSTM layer ----------------
// Grid: 128 blocks (dir = blk>>6, j-tile of 8 = (blk&63)*8), 256 threads.
// Per thread: 2 batch rows (bb, bb+32) x 1 j x 4 gates. c-state in registers,
// h ping-pong in global (.cg to bypass incoherent L1), one grid barrier/step.
__global__ __launch_bounds__(256)
void word_layer_persist(const float* __restrict__ Whh0, const float* __restrict__ Whh1,
                        const float* __restrict__ XGf, const float* __restrict__ XGb,
                        const int* __restrict__ lens, float* __restrict__ Hout)
{
    __shared__ float hs[64][68];
    __shared__ float ws[32][68];

    const int tid = threadIdx.x;
    const int jj  = tid & 7;
    const int bb  = tid >> 3;             // 0..31
    const int dir = blockIdx.x >> 6;
    const int jt  = (blockIdx.x & 63) << 3;
    const int j   = jt + jj;

    const float* W  = dir ? Whh1 : Whh0;
    const float* XG = dir ? XGb : XGf;

    const int len0 = lens[bb];
    const int len1 = lens[bb + 32];

    float hreg0 = 0.f, creg0 = 0.f;
    float hreg1 = 0.f, creg1 = 0.f;

    for (int t = 0; t < S_; ++t) {
        const float* hcur = g_hpp + (size_t)(((t    ) & 1) * 2 + dir) * (B_*H_);
        float*       hnxt = g_hpp + (size_t)(((t + 1) & 1) * 2 + dir) * (B_*H_);

        float acc[2][4];
#pragma unroll
        for (int b2 = 0; b2 < 2; ++b2)
#pragma unroll
            for (int g = 0; g < 4; ++g) acc[b2][g] = 0.f;

        for (int k0 = 0; k0 < H_; k0 += 64) {
            // load h tile [64][64]
#pragma unroll
            for (int i = 0; i < 4; ++i) {
                const int idx = tid + i * 256;        // 0..1023
                const int r = idx >> 4, c = idx & 15;
                float4 v = __ldcg((const float4*)(hcur + (size_t)r * H_ + k0 + c * 4));
                *(float4*)&hs[r][c * 4] = v;
            }
            // load weight tile: rows = 4 gates x 8 j
#pragma unroll
            for (int i = 0; i < 2; ++i) {
                const int idx = tid + i * 256;        // 0..511
                const int w = idx >> 4, c = idx & 15;
                const int g = w >> 3, jl = w & 7;
                float4 v = *(const float4*)(W + (size_t)(g * H_ + jt + jl) * H_ + k0 + c * 4);
                *(float4*)&ws[w][c * 4] = v;
            }
            __syncthreads();
#pragma unroll
            for (int k4 = 0; k4 < 16; ++k4) {
                float4 a0 = *(const float4*)&hs[bb][k4 * 4];
                float4 a1 = *(const float4*)&hs[bb + 32][k4 * 4];
#pragma unroll
                for (int g = 0; g < 4; ++g) {
                    float4 w4 = *(const float4*)&ws[g * 8 + jj][k4 * 4];
                    acc[0][g] = fmaf(a0.x, w4.x, acc[0][g]);
                    acc[0][g] = fmaf(a0.y, w4.y, acc[0][g]);
                    acc[0][g] = fmaf(a0.z, w4.z, acc[0][g]);
                    acc[0][g] = fmaf(a0.w, w4.w, acc[0][g]);
                    acc[1][g] = fmaf(a1.x, w4.x, acc[1][g]);
                    acc[1][g] = fmaf(a1.y, w4.y, acc[1][g]);
                    acc[1][g] = fmaf(a1.z, w4.z, acc[1][g]);
                    acc[1][g] = fmaf(a1.w, w4.w, acc[1][g]);
                }
            }
            __syncthreads();
        }

        // epilogue: gate nonlinearity + masked update + Hout
#pragma unroll
        for (int b2 = 0; b2 < 2; ++b2) {
            const int b = bb + b2 * 32;
            const int len = b2 ? len1 : len0;
            const bool valid = t < len;
            const int src = (dir == 0) ? t : (valid ? (len - 1 - t) : t);
            const float* xg = XG + (size_t)(b * S_ + src) * G_ + jt + jj;
            float zi = acc[b2][0] + xg[0];
            float zf = acc[b2][1] + xg[H_];
            float zg = acc[b2][2] + xg[2*H_];
            float zo = acc[b2][3] + xg[3*H_];
            float c_old = b2 ? creg1 : creg0;
            float cn = sigf(zf) * c_old + sigf(zi) * tanhf(zg);
            float hn = sigf(zo) * tanhf(cn);
            float h_old = b2 ? hreg1 : hreg0;
            float h_out = valid ? hn : h_old;
            float c_out = valid ? cn : c_old;
            if (b2) { hreg1 = h_out; creg1 = c_out; }
            else    { hreg0 = h_out; creg0 = c_out; }
            __stcg(hnxt + (size_t)b * H_ + j, h_out);
            if (dir == 0) {
                Hout[(size_t)(b * S_ + t) * CH_ + j] = valid ? hn : 0.f;
            } else if (valid) {
                Hout[(size_t)(b * S_ + src) * CH_ + H_ + j] = hn;
            }
        }

        // grid barrier (skip after last step)
        if (t < S_ - 1) {
            __syncthreads();
            if (tid == 0) {
                __threadfence();
                atomicAdd(&g_bar, 1u);
                const unsigned tgt = (unsigned)(t + 1) * (unsigned)NBLK_;
                volatile unsigned* p = &g_bar;
                while (*p < tgt) __nanosleep(64);
            }
            __syncthreads();
        }
    }
}

// ---------------- word embedding gather ----------------
__global__ void embed_words(const int* __restrict__ words, const float* __restrict__ emb)
{
    const int m = blockIdx.x;
    const int e = threadIdx.x;
    g_Xemb[(size_t)m*E_ + e] = emb[(size_t)words[m]*E_ + e];
}

// ---------------- char LSTM gate step ----------------
__global__ void char_gate(const int* __restrict__ chars, const int* __restrict__ clens,
                          const float* __restrict__ cbias, int t, int useZ)
{
    const int n = blockIdx.y;
    if (t >= clens[n]) return;                 // frozen row: skip
    const int j = blockIdx.x * blockDim.x + threadIdx.x;   // 0..1023
    const int tok = chars[n * Wc_ + t];
    const float* p = g_P + (size_t)tok * CG_;
    float zi = p[j]        + cbias[j];
    float zf = p[CH_+j]    + cbias[CH_+j];
    float zg = p[2*CH_+j]  + cbias[2*CH_+j];
    float zo = p[3*CH_+j]  + cbias[3*CH_+j];
    if (useZ) {
        const float* Z = g_Zc + (size_t)n * CG_;
        zi += Z[j]; zf += Z[CH_+j]; zg += Z[2*CH_+j]; zo += Z[3*CH_+j];
    }
    float c  = g_cc[(size_t)n*CH_+j];
    float cn = sigf(zf)*c + sigf(zi)*tanhf(zg);
    float hn = sigf(zo)*tanhf(cn);
    g_cc[(size_t)n*CH_+j] = cn;
    g_ch[(size_t)n*CH_+j] = hn;
}

// ---------------- final head: out = (Hword + valid*Hchar) @ lin_W.T + lin_b ----
__global__ __launch_bounds__(256)
void final_linear(const int* __restrict__ wnum, const float* __restrict__ W,
                  const float* __restrict__ bias, float* __restrict__ out)
{
    const int row = blockIdx.x;         // 0..8191
    const int b = row >> 7;
    const int s = row & (S_ - 1);
    const bool valid = s < wnum[b];
    __shared__ float v[CH_];
    __shared__ float sred[8*NC_];
    const int tid = threadIdx.x;
    for (int j = tid; j < CH_; j += 256) {
        float x = g_H1[(size_t)row*CH_ + j];
        if (valid) x += g_ch[(size_t)row*CH_ + j];
        v[j] = x;
    }
    __syncthreads();
    float acc[NC_];
#pragma unroll
    for (int c2 = 0; c2 < NC_; ++c2) acc[c2] = 0.f;
    for (int j = tid; j < CH_; j += 256) {
        float x = v[j];
#pragma unroll
        for (int c2 = 0; c2 < NC_; ++c2)
            acc[c2] = fmaf(x, W[c2*CH_ + j], acc[c2]);
    }
#pragma unroll
    for (int c2 = 0; c2 < NC_; ++c2)
#pragma unroll
        for (int off = 16; off > 0; off >>= 1)
            acc[c2] += __shfl_down_sync(0xffffffffu, acc[c2], off);
    const int lane = tid & 31, w = tid >> 5;
    if (lane == 0)
#pragma unroll
        for (int c2 = 0; c2 < NC_; ++c2) sred[w*NC_ + c2] = acc[c2];
    __syncthreads();
    if (tid < NC_) {
        float sum = bias[tid];
#pragma unroll
        for (int w2 = 0; w2 < 8; ++w2) sum += sred[w2*NC_ + tid];
        out[(size_t)row*NC_ + tid] = sum;
    }
}

// ================================================================================
extern "C" void kernel_launch(void* const* d_in, const int* in_sizes, int n_in,
                              void* d_out, int out_size)
{
    (void)in_sizes; (void)n_in; (void)out_size;
    const int*   words     = (const int*)  d_in[0];
    const int*   words_num = (const int*)  d_in[1];
    const int*   chars     = (const int*)  d_in[2];
    const int*   char_lens = (const int*)  d_in[3];
    const float* word_emb  = (const float*)d_in[4];
    const float* char_emb  = (const float*)d_in[5];
    const float* l0_Wih    = (const float*)d_in[6];
    const float* l0_Whh    = (const float*)d_in[7];
    const float* l0_b      = (const float*)d_in[8];
    const float* l1_Wih    = (const float*)d_in[9];
    const float* l1_Whh    = (const float*)d_in[10];
    const float* l1_b      = (const float*)d_in[11];
    const float* c_Wih     = (const float*)d_in[12];
    const float* c_Whh     = (const float*)d_in[13];
    const float* c_b       = (const float*)d_in[14];
    const float* lin_W     = (const float*)d_in[15];
    const float* lin_b     = (const float*)d_in[16];
    float* out = (float*)d_out;

    float *Xemb, *XGf, *XGb, *H0, *H1, *hpp, *P, *Zc, *ch, *cc;
    unsigned* bar;
    cudaGetSymbolAddress((void**)&Xemb, g_Xemb);
    cudaGetSymbolAddress((void**)&XGf,  g_XGf);
    cudaGetSymbolAddress((void**)&XGb,  g_XGb);
    cudaGetSymbolAddress((void**)&H0,   g_H0);
    cudaGetSymbolAddress((void**)&H1,   g_H1);
    cudaGetSymbolAddress((void**)&hpp,  g_hpp);
    cudaGetSymbolAddress((void**)&bar,  g_bar);
    cudaGetSymbolAddress((void**)&P,    g_P);
    cudaGetSymbolAddress((void**)&Zc,   g_Zc);
    cudaGetSymbolAddress((void**)&ch,   g_ch);
    cudaGetSymbolAddress((void**)&cc,   g_cc);

    // ---- word embeddings ----
    embed_words<<<NW_, E_>>>(words, word_emb);

    // ---- word BiLSTM layer 0 (input: Xemb, K=256) ----
    {
        const float* Wih0 = l0_Wih;
        const float* Wih1 = l0_Wih + (size_t)G_ * E_;
        const float* Whh0 = l0_Whh;
        const float* Whh1 = l0_Whh + (size_t)G_ * H_;
        sgemm128<<<dim3(G_/128, NW_/128), 256>>>(Xemb, Wih0, XGf, l0_b,      NW_, G_, E_);
        sgemm128<<<dim3(G_/128, NW_/128), 256>>>(Xemb, Wih1, XGb, l0_b + G_, NW_, G_, E_);
        cudaMemsetAsync(H0,  0, (size_t)NW_*CH_*sizeof(float), 0);
        cudaMemsetAsync(hpp, 0, (size_t)2*2*B_*H_*sizeof(float), 0);
        cudaMemsetAsync(bar, 0, sizeof(unsigned), 0);
        word_layer_persist<<<NBLK_, 256>>>(Whh0, Whh1, XGf, XGb, words_num, H0);
    }

    // ---- word BiLSTM layer 1 (input: H0, K=1024) ----
    {
        const float* Wih0 = l1_Wih;
        const float* Wih1 = l1_Wih + (size_t)G_ * CH_;
        const float* Whh0 = l1_Whh;
        const float* Whh1 = l1_Whh + (size_t)G_ * H_;
        sgemm128<<<dim3(G_/128, NW_/128), 256>>>(H0, Wih0, XGf, l1_b,      NW_, G_, CH_);
        sgemm128<<<dim3(G_/128, NW_/128), 256>>>(H0, Wih1, XGb, l1_b + G_, NW_, G_, CH_);
        cudaMemsetAsync(H1,  0, (size_t)NW_*CH_*sizeof(float), 0);
        cudaMemsetAsync(hpp, 0, (size_t)2*2*B_*H_*sizeof(float), 0);
        cudaMemsetAsync(bar, 0, sizeof(unsigned), 0);
        word_layer_persist<<<NBLK_, 256>>>(Whh0, Whh1, XGf, XGb, words_num, H1);
    }

    // ---- char LSTM over 8192 sequences of length 16 ----
    sgemm128<<<dim3(CG_/128, 1), 256>>>(char_emb, c_Wih, P, nullptr, 128, CG_, E_);
    cudaMemsetAsync(ch, 0, (size_t)NW_*CH_*sizeof(float), 0);
    cudaMemsetAsync(cc, 0, (size_t)NW_*CH_*sizeof(float), 0);
    for (int t = 0; t < Wc_; ++t) {
        if (t > 0)
            sgemm128<<<dim3(CG_/128, NW_/128), 256>>>(ch, c_Whh, Zc, nullptr, NW_, CG_, CH_);
        char_gate<<<dim3(CH_/256, NW_), 256>>>(chars, char_lens, c_b, t, t > 0);
    }

    // ---- head ----
    final_linear<<<NW_, 256>>>(words_num, lin_W, lin_b, out);
}

// round 3
// speedup vs baseline: 1.6290x; 1.5438x over previous
#include <cuda_runtime.h>
#include <cuda_bf16.h>
#include <cstddef>

// Problem constants
#define B_   64
#define S_   128
#define Wc_  16
#define E_   256
#define H_   512
#define NC_  20
#define NW_  (B_*S_)        // 8192 words total
#define G_   (4*H_)         // 2048 word-LSTM gate width
#define CH_  (2*H_)         // 1024 char-LSTM hidden
#define CG_  (4*CH_)        // 4096 char-LSTM gate width

#define NBLK_ 128           // persistent word-layer blocks (2 dirs x 64 j-tiles)

// ---------------- scratch (static device globals; no allocation) ----------------
__device__ float g_Xemb[(size_t)NW_*E_];     // word embeddings     [8192,256]
__device__ float g_XGf [(size_t)NW_*G_];     // fwd x-gates         [8192,2048]
__device__ float g_XGb [(size_t)NW_*G_];     // bwd x-gates         [8192,2048]
__device__ float g_H0  [(size_t)NW_*CH_];    // layer0 output       [8192,1024]
__device__ float g_H1  [(size_t)NW_*CH_];    // layer1 output       [8192,1024]
__device__ float g_hpp[(size_t)2*2*B_*H_];   // h ping-pong [buf][dir][64,512]
__device__ unsigned g_bar;                   // grid barrier counter
__device__ float g_P  [(size_t)128*CG_];     // char_emb @ c_Wih.T  [128,4096]
__device__ float g_Zc [(size_t)NW_*CG_];     // char recurrent gates[8192,4096] (sorted slots)
__device__ float g_ch [(size_t)NW_*CH_];     // char h state (sorted slots)
__device__ float g_cc [(size_t)NW_*CH_];     // char c state (sorted slots)

// ---- length-sort bookkeeping for char-path compaction ----
__device__ int g_hist[Wc_ + 1];              // histogram of lens (1..16)
__device__ int g_off [Wc_ + 1];              // scatter cursors (descending-len order)
__device__ int g_act [Wc_ + 1];              // A_t = #{len >= t+1}
__device__ int g_perm [NW_];                 // slot -> original row
__device__ int g_iperm[NW_];                 // original row -> slot
__device__ int g_slen [NW_];                 // sorted lens (descending)

__device__ __forceinline__ float sigf(float x) { return 1.f / (1.f + __expf(-x)); }

// ---------------- counting sort by char_lens (descending) ----------------
__global__ void hist_k(const int* __restrict__ clens)
{
    const int i = blockIdx.x * blockDim.x + threadIdx.x;
    if (i < NW_) atomicAdd(&g_hist[clens[i]], 1);
}
__global__ void scan_k()
{
    if (threadIdx.x == 0) {
        int off = 0;
        for (int len = Wc_; len >= 1; --len) { g_off[len] = off; off += g_hist[len]; }
        for (int t = 0; t <= Wc_; ++t) {
            int a = 0;
            for (int l = t + 1; l <= Wc_; ++l) a += g_hist[l];
            g_act[t] = a;
        }
    }
}
__global__ void scatter_k(const int* __restrict__ clens)
{
    const int i = blockIdx.x * blockDim.x + threadIdx.x;
    if (i < NW_) {
        const int len = clens[i];
        const int s = atomicAdd(&g_off[len], 1);
        g_perm[s] = i;
        g_iperm[i] = s;
        g_slen[s] = len;
    }
}

// ---------------- SGEMM: C[M,N] = A[M,K] @ B[N,K]^T (+bias[n]) ----------------
// 128x128 tile, 256 threads, 8x8 microtile, K-chunk 8, reg-prefetch double buffer.
// If act != nullptr, blocks whose row tile starts at/after act[step] exit early.
__global__ __launch_bounds__(256)
void sgemm128(const float* __restrict__ A, const float* __restrict__ Bm,
              float* __restrict__ C, const float* __restrict__ bias,
              int M, int N, int K, const int* __restrict__ act, int step)
{
    const int row0 = blockIdx.y * 128;
    if (act && row0 >= act[step]) return;

    __shared__ float As[8][128];
    __shared__ float Bs[8][128];
    const int tid = threadIdx.x;
    const int tx  = tid & 15;
    const int ty  = tid >> 4;
    const int col0 = blockIdx.x * 128;
    const int lr = tid >> 1;
    const int lk = (tid & 1) * 4;

    const float* Ap = A  + (size_t)(row0 + lr) * K + lk;
    const float* Bp = Bm + (size_t)(col0 + lr) * K + lk;

    float acc[8][8];
#pragma unroll
    for (int i = 0; i < 8; ++i)
#pragma unroll
        for (int j = 0; j < 8; ++j) acc[i][j] = 0.f;

    {
        float4 a = *(const float4*)Ap;
        float4 b = *(const float4*)Bp;
        As[lk+0][lr] = a.x; As[lk+1][lr] = a.y; As[lk+2][lr] = a.z; As[lk+3][lr] = a.w;
        Bs[lk+0][lr] = b.x; Bs[lk+1][lr] = b.y; Bs[lk+2][lr] = b.z; Bs[lk+3][lr] = b.w;
    }
    __syncthreads();

    int k0 = 0;
    while (true) {
        const int kn = k0 + 8;
        const bool more = kn < K;
        float4 an, bn;
        if (more) { an = *(const float4*)(Ap + kn); bn = *(const float4*)(Bp + kn); }
#pragma unroll
        for (int k = 0; k < 8; ++k) {
            float4 a0 = *(const float4*)&As[k][ty*8];
            float4 a1 = *(const float4*)&As[k][ty*8+4];
            float4 b0 = *(const float4*)&Bs[k][tx*8];
            float4 b1 = *(const float4*)&Bs[k][tx*8+4];
            float av[8] = {a0.x,a0.y,a0.z,a0.w,a1.x,a1.y,a1.z,a1.w};
            float bv[8] = {b0.x,b0.y,b0.z,b0.w,b1.x,b1.y,b1.z,b1.w};
#pragma unroll
            for (int i = 0; i < 8; ++i)
#pragma unroll
                for (int j = 0; j < 8; ++j)
                    acc[i][j] = fmaf(av[i], bv[j], acc[i][j]);
        }
        if (!more) break;
        __syncthreads();
        As[lk+0][lr] = an.x; As[lk+1][lr] = an.y; As[lk+2][lr] = an.z; As[lk+3][lr] = an.w;
        Bs[lk+0][lr] = bn.x; Bs[lk+1][lr] = bn.y; Bs[lk+2][lr] = bn.z; Bs[lk+3][lr] = bn.w;
        __syncthreads();
        k0 = kn;
    }

    float bv0[8];
#pragma unroll
    for (int j = 0; j < 8; ++j) bv0[j] = bias ? bias[col0 + tx*8 + j] : 0.f;
#pragma unroll
    for (int i = 0; i < 8; ++i) {
        const int r = row0 + ty*8 + i;
        float4 o0, o1;
        o0.x = acc[i][0]+bv0[0]; o0.y = acc[i][1]+bv0[1];
        o0.z = acc[i][2]+bv0[2]; o0.w = acc[i][3]+bv0[3];
        o1.x = acc[i][4]+bv0[4]; o1.y = acc[i][5]+bv0[5];
        o1.z = acc[i][6]+bv0[6]; o1.w = acc[i][7]+bv0[7];
        *(float4*)(C + (size_t)r*N + col0 + tx*8)     = o0;
        *(float4*)(C + (size_t)r*N + col0 + tx*8 + 4) = o1;
    }
}

// ---------------- persistent word BiLSTM layer ----------------
__global__ __launch_bounds__(256)
void word_layer_persist(const float* __restrict__ Whh0, const float* __restrict__ Whh1,
                        const float* __restrict__ XGf, const float* __restrict__ XGb,
                        const int* __restrict__ lens, float* __restrict__ Hout)
{
    __shared__ float hs[64][68];
    __shared__ float ws[32][68];

    const int tid = threadIdx.x;
    const int jj  = tid & 7;
    const int bb  = tid >> 3;             // 0..31
    const int dir = blockIdx.x >> 6;
    const int jt  = (blockIdx.x & 63) << 3;
    const int j   = jt + jj;

    const float* W  = dir ? Whh1 : Whh0;
    const float* XG = dir ? XGb : XGf;

    const int len0 = lens[bb];
    const int len1 = lens[bb + 32];

    float hreg0 = 0.f, creg0 = 0.f;
    float hreg1 = 0.f, creg1 = 0.f;

    for (int t = 0; t < S_; ++t) {
        const float* hcur = g_hpp + (size_t)(((t    ) & 1) * 2 + dir) * (B_*H_);
        float*       hnxt = g_hpp + (size_t)(((t + 1) & 1) * 2 + dir) * (B_*H_);

        float acc[2][4];
#pragma unroll
        for (int b2 = 0; b2 < 2; ++b2)
#pragma unroll
            for (int g = 0; g < 4; ++g) acc[b2][g] = 0.f;

        for (int k0 = 0; k0 < H_; k0 += 64) {
#pragma unroll
            for (int i = 0; i < 4; ++i) {
                const int idx = tid + i * 256;
                const int r = idx >> 4, c = idx & 15;
                float4 v = __ldcg((const float4*)(hcur + (size_t)r * H_ + k0 + c * 4));
                *(float4*)&hs[r][c * 4] = v;
            }
#pragma unroll
            for (int i = 0; i < 2; ++i) {
                const int idx = tid + i * 256;
                const int w = idx >> 4, c = idx & 15;
                const int g = w >> 3, jl = w & 7;
                float4 v = *(const float4*)(W + (size_t)(g * H_ + jt + jl) * H_ + k0 + c * 4);
                *(float4*)&ws[w][c * 4] = v;
            }
            __syncthreads();
#pragma unroll
            for (int k4 = 0; k4 < 16; ++k4) {
                float4 a0 = *(const float4*)&hs[bb][k4 * 4];
                float4 a1 = *(const float4*)&hs[bb + 32][k4 * 4];
#pragma unroll
                for (int g = 0; g < 4; ++g) {
                    float4 w4 = *(const float4*)&ws[g * 8 + jj][k4 * 4];
                    acc[0][g] = fmaf(a0.x, w4.x, acc[0][g]);
                    acc[0][g] = fmaf(a0.y, w4.y, acc[0][g]);
                    acc[0][g] = fmaf(a0.z, w4.z, acc[0][g]);
                    acc[0][g] = fmaf(a0.w, w4.w, acc[0][g]);
                    acc[1][g] = fmaf(a1.x, w4.x, acc[1][g]);
                    acc[1][g] = fmaf(a1.y, w4.y, acc[1][g]);
                    acc[1][g] = fmaf(a1.z, w4.z, acc[1][g]);
                    acc[1][g] = fmaf(a1.w, w4.w, acc[1][g]);
                }
            }
            __syncthreads();
        }

#pragma unroll
        for (int b2 = 0; b2 < 2; ++b2) {
            const int b = bb + b2 * 32;
            const int len = b2 ? len1 : len0;
            const bool valid = t < len;
            const int src = (dir == 0) ? t : (valid ? (len - 1 - t) : t);
            const float* xg = XG + (size_t)(b * S_ + src) * G_ + jt + jj;
            float zi = acc[b2][0] + xg[0];
            float zf = acc[b2][1] + xg[H_];
            float zg = acc[b2][2] + xg[2*H_];
            float zo = acc[b2][3] + xg[3*H_];
            float c_old = b2 ? creg1 : creg0;
            float cn = sigf(zf) * c_old + sigf(zi) * tanhf(zg);
            float hn = sigf(zo) * tanhf(cn);
            float h_old = b2 ? hreg1 : hreg0;
            float h_out = valid ? hn : h_old;
            float c_out = valid ? cn : c_old;
            if (b2) { hreg1 = h_out; creg1 = c_out; }
            else    { hreg0 = h_out; creg0 = c_out; }
            __stcg(hnxt + (size_t)b * H_ + j, h_out);
            if (dir == 0) {
                Hout[(size_t)(b * S_ + t) * CH_ + j] = valid ? hn : 0.f;
            } else if (valid) {
                Hout[(size_t)(b * S_ + src) * CH_ + H_ + j] = hn;
            }
        }

        if (t < S_ - 1) {
            __syncthreads();
            if (tid == 0) {
                __threadfence();
                atomicAdd(&g_bar, 1u);
                const unsigned tgt = (unsigned)(t + 1) * (unsigned)NBLK_;
                volatile unsigned* p = &g_bar;
                while (*p < tgt) __nanosleep(64);
            }
            __syncthreads();
        }
    }
}

// ---------------- word embedding gather ----------------
__global__ void embed_words(const int* __restrict__ words, const float* __restrict__ emb)
{
    const int m = blockIdx.x;
    const int e = threadIdx.x;
    g_Xemb[(size_t)m*E_ + e] = emb[(size_t)words[m]*E_ + e];
}

// ---------------- char LSTM gate step (sorted slots) ----------------
__global__ void char_gate(const int* __restrict__ chars,
                          const float* __restrict__ cbias, int t, int useZ)
{
    const int n = blockIdx.y;                  // slot
    if (t >= g_slen[n]) return;                // sorted: frozen slots are a suffix
    const int j = blockIdx.x * blockDim.x + threadIdx.x;   // 0..1023
    const int tok = chars[g_perm[n] * Wc_ + t];
    const float* p = g_P + (size_t)tok * CG_;
    float zi = p[j]        + cbias[j];
    float zf = p[CH_+j]    + cbias[CH_+j];
    float zg = p[2*CH_+j]  + cbias[2*CH_+j];
    float zo = p[3*CH_+j]  + cbias[3*CH_+j];
    if (useZ) {
        const float* Z = g_Zc + (size_t)n * CG_;
        zi += Z[j]; zf += Z[CH_+j]; zg += Z[2*CH_+j]; zo += Z[3*CH_+j];
    }
    float c  = g_cc[(size_t)n*CH_+j];
    float cn = sigf(zf)*c + sigf(zi)*tanhf(zg);
    float hn = sigf(zo)*tanhf(cn);
    g_cc[(size_t)n*CH_+j] = cn;
    g_ch[(size_t)n*CH_+j] = hn;
}

// ---------------- final head: out = (Hword + valid*Hchar) @ lin_W.T + lin_b ----
__global__ __launch_bounds__(256)
void final_linear(const int* __restrict__ wnum, const float* __restrict__ W,
                  const float* __restrict__ bias, float* __restrict__ out)
{
    const int row = blockIdx.x;         // 0..8191
    const int b = row >> 7;
    const int s = row & (S_ - 1);
    const bool valid = s < wnum[b];
    const int slot = g_iperm[row];
    __shared__ float v[CH_];
    __shared__ float sred[8*NC_];
    const int tid = threadIdx.x;
    for (int j = tid; j < CH_; j += 256) {
        float x = g_H1[(size_t)row*CH_ + j];
        if (valid) x += g_ch[(size_t)slot*CH_ + j];
        v[j] = x;
    }
    __syncthreads();
    float acc[NC_];
#pragma unroll
    for (int c2 = 0; c2 < NC_; ++c2) acc[c2] = 0.f;
    for (int j = tid; j < CH_; j += 256) {
        float x = v[j];
#pragma unroll
        for (int c2 = 0; c2 < NC_; ++c2)
            acc[c2] = fmaf(x, W[c2*CH_ + j], acc[c2]);
    }
#pragma unroll
    for (int c2 = 0; c2 < NC_; ++c2)
#pragma unroll
        for (int off = 16; off > 0; off >>= 1)
            acc[c2] += __shfl_down_sync(0xffffffffu, acc[c2], off);
    const int lane = tid & 31, w = tid >> 5;
    if (lane == 0)
#pragma unroll
        for (int c2 = 0; c2 < NC_; ++c2) sred[w*NC_ + c2] = acc[c2];
    __syncthreads();
    if (tid < NC_) {
        float sum = bias[tid];
#pragma unroll
        for (int w2 = 0; w2 < 8; ++w2) sum += sred[w2*NC_ + tid];
        out[(size_t)row*NC_ + tid] = sum;
    }
}

// ================================================================================
extern "C" void kernel_launch(void* const* d_in, const int* in_sizes, int n_in,
                              void* d_out, int out_size)
{
    (void)in_sizes; (void)n_in; (void)out_size;
    const int*   words     = (const int*)  d_in[0];
    const int*   words_num = (const int*)  d_in[1];
    const int*   chars     = (const int*)  d_in[2];
    const int*   char_lens = (const int*)  d_in[3];
    const float* word_emb  = (const float*)d_in[4];
    const float* char_emb  = (const float*)d_in[5];
    const float* l0_Wih    = (const float*)d_in[6];
    const float* l0_Whh    = (const float*)d_in[7];
    const float* l0_b      = (const float*)d_in[8];
    const float* l1_Wih    = (const float*)d_in[9];
    const float* l1_Whh    = (const float*)d_in[10];
    const float* l1_b      = (const float*)d_in[11];
    const float* c_Wih     = (const float*)d_in[12];
    const float* c_Whh     = (const float*)d_in[13];
    const float* c_b       = (const float*)d_in[14];
    const float* lin_W     = (const float*)d_in[15];
    const float* lin_b     = (const float*)d_in[16];
    float* out = (float*)d_out;

    float *Xemb, *XGf, *XGb, *H0, *H1, *hpp, *P, *Zc, *ch, *cc;
    unsigned* bar;
    int *hist, *act;
    cudaGetSymbolAddress((void**)&Xemb, g_Xemb);
    cudaGetSymbolAddress((void**)&XGf,  g_XGf);
    cudaGetSymbolAddress((void**)&XGb,  g_XGb);
    cudaGetSymbolAddress((void**)&H0,   g_H0);
    cudaGetSymbolAddress((void**)&H1,   g_H1);
    cudaGetSymbolAddress((void**)&hpp,  g_hpp);
    cudaGetSymbolAddress((void**)&bar,  g_bar);
    cudaGetSymbolAddress((void**)&P,    g_P);
    cudaGetSymbolAddress((void**)&Zc,   g_Zc);
    cudaGetSymbolAddress((void**)&ch,   g_ch);
    cudaGetSymbolAddress((void**)&cc,   g_cc);
    cudaGetSymbolAddress((void**)&hist, g_hist);
    cudaGetSymbolAddress((void**)&act,  g_act);

    // ---- char length sort (independent; run first) ----
    cudaMemsetAsync(hist, 0, (Wc_ + 1) * sizeof(int), 0);
    hist_k<<<NW_/256, 256>>>(char_lens);
    scan_k<<<1, 32>>>();
    scatter_k<<<NW_/256, 256>>>(char_lens);

    // ---- word embeddings ----
    embed_words<<<NW_, E_>>>(words, word_emb);

    // ---- word BiLSTM layer 0 (input: Xemb, K=256) ----
    {
        const float* Wih0 = l0_Wih;
        const float* Wih1 = l0_Wih + (size_t)G_ * E_;
        const float* Whh0 = l0_Whh;
        const float* Whh1 = l0_Whh + (size_t)G_ * H_;
        sgemm128<<<dim3(G_/128, NW_/128), 256>>>(Xemb, Wih0, XGf, l0_b,      NW_, G_, E_, nullptr, 0);
        sgemm128<<<dim3(G_/128, NW_/128), 256>>>(Xemb, Wih1, XGb, l0_b + G_, NW_, G_, E_, nullptr, 0);
        cudaMemsetAsync(H0,  0, (size_t)NW_*CH_*sizeof(float), 0);
        cudaMemsetAsync(hpp, 0, (size_t)2*2*B_*H_*sizeof(float), 0);
        cudaMemsetAsync(bar, 0, sizeof(unsigned), 0);
        word_layer_persist<<<NBLK_, 256>>>(Whh0, Whh1, XGf, XGb, words_num, H0);
    }

    // ---- word BiLSTM layer 1 (input: H0, K=1024) ----
    {
        const float* Wih0 = l1_Wih;
        const float* Wih1 = l1_Wih + (size_t)G_ * CH_;
        const float* Whh0 = l1_Whh;
        const float* Whh1 = l1_Whh + (size_t)G_ * H_;
        sgemm128<<<dim3(G_/128, NW_/128), 256>>>(H0, Wih0, XGf, l1_b,      NW_, G_, CH_, nullptr, 0);
        sgemm128<<<dim3(G_/128, NW_/128), 256>>>(H0, Wih1, XGb, l1_b + G_, NW_, G_, CH_, nullptr, 0);
        cudaMemsetAsync(H1,  0, (size_t)NW_*CH_*sizeof(float), 0);
        cudaMemsetAsync(hpp, 0, (size_t)2*2*B_*H_*sizeof(float), 0);
        cudaMemsetAsync(bar, 0, sizeof(unsigned), 0);
        word_layer_persist<<<NBLK_, 256>>>(Whh0, Whh1, XGf, XGb, words_num, H1);
    }

    // ---- char LSTM over 8192 sequences of length<=16, sorted by length desc ----
    sgemm128<<<dim3(CG_/128, 1), 256>>>(char_emb, c_Wih, P, nullptr, 128, CG_, E_, nullptr, 0);
    cudaMemsetAsync(ch, 0, (size_t)NW_*CH_*sizeof(float), 0);
    cudaMemsetAsync(cc, 0, (size_t)NW_*CH_*sizeof(float), 0);
    for (int t = 0; t < Wc_; ++t) {
        if (t > 0)
            sgemm128<<<dim3(CG_/128, NW_/128), 256>>>(ch, c_Whh, Zc, nullptr, NW_, CG_, CH_, act, t);
        char_gate<<<dim3(CH_/256, NW_), 256>>>(chars, c_b, t, t > 0);
    }

    // ---- head ----
    final_linear<<<NW_, 256>>>(words_num, lin_W, lin_b, out);
}

// round 4
// speedup vs baseline: 2.2388x; 1.3743x over previous
#include <cuda_runtime.h>
#include <cuda_bf16.h>
#include <cstdint>
#include <cstddef>

// Problem constants
#define B_   64
#define S_   128
#define Wc_  16
#define E_   256
#define H_   512
#define NC_  20
#define NW_  (B_*S_)        // 8192 words total
#define G_   (4*H_)         // 2048 word-LSTM gate width
#define CH_  (2*H_)         // 1024 char-LSTM hidden
#define CG_  (4*CH_)        // 4096 char-LSTM gate width

#define NBLK_ 128           // persistent word-layer blocks

// ---------------- scratch (static device globals; no allocation) ----------------
__device__ __nv_bfloat16 g_Xembs[(size_t)NW_*3*E_];    // split word emb   [8192,768]
__device__ float g_XGf [(size_t)NW_*G_];               // fwd x-gates      [8192,2048]
__device__ float g_XGb [(size_t)NW_*G_];               // bwd x-gates      [8192,2048]
__device__ float g_H0  [(size_t)NW_*CH_];              // layer0 out fp32 (scratch)
__device__ __nv_bfloat16 g_H0s[(size_t)NW_*3*CH_];     // layer0 out split [8192,3072]
__device__ float g_H1  [(size_t)NW_*CH_];              // layer1 output    [8192,1024]
__device__ float g_hpp[(size_t)2*2*B_*H_];             // h ping-pong
__device__ unsigned g_bar;                             // grid barrier counter
__device__ float g_P  [(size_t)128*CG_];               // char_emb @ c_Wih.T [128,4096]
__device__ float g_Zc [(size_t)NW_*CG_];               // char recurrent gates (sorted)
__device__ float g_ch [(size_t)NW_*CH_];               // char h fp32 (sorted slots)
__device__ __nv_bfloat16 g_hs[(size_t)NW_*3*CH_];      // char h split [8192,3072]
__device__ float g_cc [(size_t)NW_*CH_];               // char c state (sorted)
__device__ __nv_bfloat16 g_Wc2   [(size_t)CG_*3*CH_];  // c_Whh split  [4096,3072]
__device__ __nv_bfloat16 g_Wih0s [(size_t)2*G_*3*E_];  // l0_Wih split [2][2048,768]
__device__ __nv_bfloat16 g_Wih1s [(size_t)2*G_*3*CH_]; // l1_Wih split [2][2048,3072]

// ---- length-sort bookkeeping ----
__device__ int g_hist[Wc_ + 1];
__device__ int g_off [Wc_ + 1];
__device__ int g_act [Wc_ + 1];
__device__ int g_perm [NW_];
__device__ int g_iperm[NW_];
__device__ int g_slen [NW_];

__device__ __forceinline__ float sigf(float x) { return 1.f / (1.f + __expf(-x)); }

__device__ __forceinline__ void bf16split(float x, __nv_bfloat16& hi, __nv_bfloat16& lo)
{
    hi = __float2bfloat16(x);
    lo = __float2bfloat16(x - __bfloat162float(hi));
}

// ---------------- counting sort by char_lens (descending) ----------------
__global__ void hist_k(const int* __restrict__ clens)
{
    const int i = blockIdx.x * blockDim.x + threadIdx.x;
    if (i < NW_) atomicAdd(&g_hist[clens[i]], 1);
}
__global__ void scan_k()
{
    if (threadIdx.x == 0) {
        int off = 0;
        for (int len = Wc_; len >= 1; --len) { g_off[len] = off; off += g_hist[len]; }
        for (int t = 0; t <= Wc_; ++t) {
            int a = 0;
            for (int l = t + 1; l <= Wc_; ++l) a += g_hist[l];
            g_act[t] = a;
        }
    }
}
__global__ void scatter_k(const int* __restrict__ clens)
{
    const int i = blockIdx.x * blockDim.x + threadIdx.x;
    if (i < NW_) {
        const int len = clens[i];
        const int s = atomicAdd(&g_off[len], 1);
        g_perm[s] = i;
        g_iperm[i] = s;
        g_slen[s] = len;
    }
}

// ---------------- fp32 -> bf16x3 split of a weight matrix ----------------
// amode=1 (A side): [hi | hi | lo];  amode=0 (B side): [hi | lo | hi]
__global__ void split_k(const float* __restrict__ src, __nv_bfloat16* __restrict__ dst,
                        int K, int total, int amode)
{
    const int i = blockIdx.x * blockDim.x + threadIdx.x;
    if (i >= total) return;
    const int n = i / K, k = i % K;
    __nv_bfloat16 hi, lo;
    bf16split(src[i], hi, lo);
    const size_t base = (size_t)n * 3 * K;
    if (amode) { dst[base + k] = hi; dst[base + K + k] = hi; dst[base + 2*K + k] = lo; }
    else       { dst[base + k] = hi; dst[base + K + k] = lo; dst[base + 2*K + k] = hi; }
}

// ---------------- bf16 tensor-core GEMM: C[M,N] = A'[M,K] @ B'[N,K]^T ----------
// A',B' are bf16x3-split operands (K already tripled by caller). fp32 accumulate.
// 128x128 block tile, 8 warps (2x4), warp tile 64x32, K-chunk 32, mma.m16n8k16.
// If act != nullptr, row tiles at/after act[step] exit early.
__global__ __launch_bounds__(256)
void hgemm(const __nv_bfloat16* __restrict__ A, const __nv_bfloat16* __restrict__ Bm,
           float* __restrict__ C, int M, int N, int K,
           const int* __restrict__ act, int step)
{
    const int row0 = blockIdx.y * 128;
    if (act && row0 >= act[step]) return;
    const int col0 = blockIdx.x * 128;

    __shared__ __nv_bfloat16 As[128][40];
    __shared__ __nv_bfloat16 Bs[128][40];

    const int tid  = threadIdx.x;
    const int lane = tid & 31;
    const int wid  = tid >> 5;
    const int wm   = (wid & 1) * 64;
    const int wn   = (wid >> 1) * 32;

    float acc[4][4][4];
#pragma unroll
    for (int mi = 0; mi < 4; ++mi)
#pragma unroll
        for (int ni = 0; ni < 4; ++ni)
#pragma unroll
            for (int f = 0; f < 4; ++f) acc[mi][ni][f] = 0.f;

    const int lr = tid >> 2;          // 0..63
    const int lc = (tid & 3) * 8;     // 0,8,16,24

    for (int k0 = 0; k0 < K; k0 += 32) {
#pragma unroll
        for (int rep = 0; rep < 2; ++rep) {
            const int r = lr + rep * 64;
            *(uint4*)&As[r][lc] = *(const uint4*)&A [(size_t)(row0 + r) * K + k0 + lc];
            *(uint4*)&Bs[r][lc] = *(const uint4*)&Bm[(size_t)(col0 + r) * K + k0 + lc];
        }
        __syncthreads();
#pragma unroll
        for (int ks = 0; ks < 2; ++ks) {
            uint32_t a[4][4], b[4][2];
#pragma unroll
            for (int mi = 0; mi < 4; ++mi) {
                uint32_t addr = (uint32_t)__cvta_generic_to_shared(
                    &As[wm + mi*16 + (lane & 15)][ks*16 + (lane >> 4) * 8]);
                asm volatile("ldmatrix.sync.aligned.m8n8.x4.shared.b16 {%0,%1,%2,%3}, [%4];"
                    : "=r"(a[mi][0]), "=r"(a[mi][1]), "=r"(a[mi][2]), "=r"(a[mi][3])
                    : "r"(addr));
            }
#pragma unroll
            for (int ni = 0; ni < 4; ++ni) {
                uint32_t addr = (uint32_t)__cvta_generic_to_shared(
                    &Bs[wn + ni*8 + (lane & 7)][ks*16 + ((lane >> 3) & 1) * 8]);
                asm volatile("ldmatrix.sync.aligned.m8n8.x2.shared.b16 {%0,%1}, [%2];"
                    : "=r"(b[ni][0]), "=r"(b[ni][1]) : "r"(addr));
            }
#pragma unroll
            for (int mi = 0; mi < 4; ++mi)
#pragma unroll
                for (int ni = 0; ni < 4; ++ni) {
                    asm volatile(
                        "mma.sync.aligned.m16n8k16.row.col.f32.bf16.bf16.f32 "
                        "{%0,%1,%2,%3}, {%4,%5,%6,%7}, {%8,%9}, {%0,%1,%2,%3};"
                        : "+f"(acc[mi][ni][0]), "+f"(acc[mi][ni][1]),
                          "+f"(acc[mi][ni][2]), "+f"(acc[mi][ni][3])
                        : "r"(a[mi][0]), "r"(a[mi][1]), "r"(a[mi][2]), "r"(a[mi][3]),
                          "r"(b[ni][0]), "r"(b[ni][1]));
                }
        }
        __syncthreads();
    }

#pragma unroll
    for (int mi = 0; mi < 4; ++mi)
#pragma unroll
        for (int ni = 0; ni < 4; ++ni) {
            const int r = row0 + wm + mi*16 + (lane >> 2);
            const int c = col0 + wn + ni*8 + (lane & 3) * 2;
            float2 v0 = make_float2(acc[mi][ni][0], acc[mi][ni][1]);
            float2 v1 = make_float2(acc[mi][ni][2], acc[mi][ni][3]);
            *(float2*)&C[(size_t)r * N + c]       = v0;
            *(float2*)&C[(size_t)(r + 8) * N + c] = v1;
        }
}

// ---------------- fp32 SGEMM (only for P = char_emb @ c_Wih.T, M=128) ----------
__global__ __launch_bounds__(256)
void sgemm128(const float* __restrict__ A, const float* __restrict__ Bm,
              float* __restrict__ C, int M, int N, int K)
{
    __shared__ float As[8][128];
    __shared__ float Bs[8][128];
    const int tid = threadIdx.x;
    const int tx  = tid & 15;
    const int ty  = tid >> 4;
    const int row0 = blockIdx.y * 128;
    const int col0 = blockIdx.x * 128;
    const int lr = tid >> 1;
    const int lk = (tid & 1) * 4;

    const float* Ap = A  + (size_t)(row0 + lr) * K + lk;
    const float* Bp = Bm + (size_t)(col0 + lr) * K + lk;

    float acc[8][8];
#pragma unroll
    for (int i = 0; i < 8; ++i)
#pragma unroll
        for (int j = 0; j < 8; ++j) acc[i][j] = 0.f;

    {
        float4 a = *(const float4*)Ap;
        float4 b = *(const float4*)Bp;
        As[lk+0][lr] = a.x; As[lk+1][lr] = a.y; As[lk+2][lr] = a.z; As[lk+3][lr] = a.w;
        Bs[lk+0][lr] = b.x; Bs[lk+1][lr] = b.y; Bs[lk+2][lr] = b.z; Bs[lk+3][lr] = b.w;
    }
    __syncthreads();

    int k0 = 0;
    while (true) {
        const int kn = k0 + 8;
        const bool more = kn < K;
        float4 an, bn;
        if (more) { an = *(const float4*)(Ap + kn); bn = *(const float4*)(Bp + kn); }
#pragma unroll
        for (int k = 0; k < 8; ++k) {
            float4 a0 = *(const float4*)&As[k][ty*8];
            float4 a1 = *(const float4*)&As[k][ty*8+4];
            float4 b0 = *(const float4*)&Bs[k][tx*8];
            float4 b1 = *(const float4*)&Bs[k][tx*8+4];
            float av[8] = {a0.x,a0.y,a0.z,a0.w,a1.x,a1.y,a1.z,a1.w};
            float bv[8] = {b0.x,b0.y,b0.z,b0.w,b1.x,b1.y,b1.z,b1.w};
#pragma unroll
            for (int i = 0; i < 8; ++i)
#pragma unroll
                for (int j = 0; j < 8; ++j)
                    acc[i][j] = fmaf(av[i], bv[j], acc[i][j]);
        }
        if (!more) break;
        __syncthreads();
        As[lk+0][lr] = an.x; As[lk+1][lr] = an.y; As[lk+2][lr] = an.z; As[lk+3][lr] = an.w;
        Bs[lk+0][lr] = bn.x; Bs[lk+1][lr] = bn.y; Bs[lk+2][lr] = bn.z; Bs[lk+3][lr] = bn.w;
        __syncthreads();
        k0 = kn;
    }

#pragma unroll
    for (int i = 0; i < 8; ++i) {
        const int r = row0 + ty*8 + i;
        float4 o0, o1;
        o0.x = acc[i][0]; o0.y = acc[i][1]; o0.z = acc[i][2]; o0.w = acc[i][3];
        o1.x = acc[i][4]; o1.y = acc[i][5]; o1.z = acc[i][6]; o1.w = acc[i][7];
        *(float4*)(C + (size_t)r*N + col0 + tx*8)     = o0;
        *(float4*)(C + (size_t)r*N + col0 + tx*8 + 4) = o1;
    }
}

// ---------------- persistent word BiLSTM layer ----------------
// bias: full l_b [2][G_]; added in epilogue (GEMMs no longer carry bias).
// Houts (optional): bf16x3 split output [8192][3072] (A-side layout).
__global__ __launch_bounds__(256)
void word_layer_persist(const float* __restrict__ Whh0, const float* __restrict__ Whh1,
                        const float* __restrict__ XGf, const float* __restrict__ XGb,
                        const int* __restrict__ lens, const float* __restrict__ bias,
                        float* __restrict__ Hout, __nv_bfloat16* __restrict__ Houts)
{
    __shared__ float hs[64][68];
    __shared__ float ws[32][68];

    const int tid = threadIdx.x;
    const int jj  = tid & 7;
    const int bb  = tid >> 3;             // 0..31
    const int dir = blockIdx.x >> 6;
    const int jt  = (blockIdx.x & 63) << 3;
    const int j   = jt + jj;

    const float* W  = dir ? Whh1 : Whh0;
    const float* XG = dir ? XGb : XGf;
    const float* bv = bias + (size_t)dir * G_;
    float bg[4];
#pragma unroll
    for (int g = 0; g < 4; ++g) bg[g] = bv[g * H_ + j];

    const int len0 = lens[bb];
    const int len1 = lens[bb + 32];

    float hreg0 = 0.f, creg0 = 0.f;
    float hreg1 = 0.f, creg1 = 0.f;

    for (int t = 0; t < S_; ++t) {
        const float* hcur = g_hpp + (size_t)(((t    ) & 1) * 2 + dir) * (B_*H_);
        float*       hnxt = g_hpp + (size_t)(((t + 1) & 1) * 2 + dir) * (B_*H_);

        float acc[2][4];
#pragma unroll
        for (int b2 = 0; b2 < 2; ++b2)
#pragma unroll
            for (int g = 0; g < 4; ++g) acc[b2][g] = 0.f;

        for (int k0 = 0; k0 < H_; k0 += 64) {
#pragma unroll
            for (int i = 0; i < 4; ++i) {
                const int idx = tid + i * 256;
                const int r = idx >> 4, c = idx & 15;
                float4 v = __ldcg((const float4*)(hcur + (size_t)r * H_ + k0 + c * 4));
                *(float4*)&hs[r][c * 4] = v;
            }
#pragma unroll
            for (int i = 0; i < 2; ++i) {
                const int idx = tid + i * 256;
                const int w = idx >> 4, c = idx & 15;
                const int g = w >> 3, jl = w & 7;
                float4 v = *(const float4*)(W + (size_t)(g * H_ + jt + jl) * H_ + k0 + c * 4);
                *(float4*)&ws[w][c * 4] = v;
            }
            __syncthreads();
#pragma unroll
            for (int k4 = 0; k4 < 16; ++k4) {
                float4 a0 = *(const float4*)&hs[bb][k4 * 4];
                float4 a1 = *(const float4*)&hs[bb + 32][k4 * 4];
#pragma unroll
                for (int g = 0; g < 4; ++g) {
                    float4 w4 = *(const float4*)&ws[g * 8 + jj][k4 * 4];
                    acc[0][g] = fmaf(a0.x, w4.x, acc[0][g]);
                    acc[0][g] = fmaf(a0.y, w4.y, acc[0][g]);
                    acc[0][g] = fmaf(a0.z, w4.z, acc[0][g]);
                    acc[0][g] = fmaf(a0.w, w4.w, acc[0][g]);
                    acc[1][g] = fmaf(a1.x, w4.x, acc[1][g]);
                    acc[1][g] = fmaf(a1.y, w4.y, acc[1][g]);
                    acc[1][g] = fmaf(a1.z, w4.z, acc[1][g]);
                    acc[1][g] = fmaf(a1.w, w4.w, acc[1][g]);
                }
            }
            __syncthreads();
        }

#pragma unroll
        for (int b2 = 0; b2 < 2; ++b2) {
            const int b = bb + b2 * 32;
            const int len = b2 ? len1 : len0;
            const bool valid = t < len;
            const int src = (dir == 0) ? t : (valid ? (len - 1 - t) : t);
            const float* xg = XG + (size_t)(b * S_ + src) * G_ + jt + jj;
            float zi = acc[b2][0] + xg[0]      + bg[0];
            float zf = acc[b2][1] + xg[H_]     + bg[1];
            float zg = acc[b2][2] + xg[2*H_]   + bg[2];
            float zo = acc[b2][3] + xg[3*H_]   + bg[3];
            float c_old = b2 ? creg1 : creg0;
            float cn = sigf(zf) * c_old + sigf(zi) * tanhf(zg);
            float hn = sigf(zo) * tanhf(cn);
            float h_old = b2 ? hreg1 : hreg0;
            float h_out = valid ? hn : h_old;
            float c_out = valid ? cn : c_old;
            if (b2) { hreg1 = h_out; creg1 = c_out; }
            else    { hreg0 = h_out; creg0 = c_out; }
            __stcg(hnxt + (size_t)b * H_ + j, h_out);
            if (dir == 0) {
                const float v = valid ? hn : 0.f;
                Hout[(size_t)(b * S_ + t) * CH_ + j] = v;
                if (Houts) {
                    __nv_bfloat16 hi, lo; bf16split(v, hi, lo);
                    const size_t base = (size_t)(b * S_ + t) * (3*CH_) + j;
                    Houts[base] = hi; Houts[base + CH_] = hi; Houts[base + 2*CH_] = lo;
                }
            } else if (valid) {
                Hout[(size_t)(b * S_ + src) * CH_ + H_ + j] = hn;
                if (Houts) {
                    __nv_bfloat16 hi, lo; bf16split(hn, hi, lo);
                    const size_t base = (size_t)(b * S_ + src) * (3*CH_) + H_ + j;
                    Houts[base] = hi; Houts[base + CH_] = hi; Houts[base + 2*CH_] = lo;
                }
            }
        }

        if (t < S_ - 1) {
            __syncthreads();
            if (tid == 0) {
                __threadfence();
                atomicAdd(&g_bar, 1u);
                const unsigned tgt = (unsigned)(t + 1) * (unsigned)NBLK_;
                volatile unsigned* p = &g_bar;
                while (*p < tgt) __nanosleep(64);
            }
            __syncthreads();
        }
    }
}

// ---------------- word embedding gather (writes split directly) ----------------
__global__ void embed_words(const int* __restrict__ words, const float* __restrict__ emb)
{
    const int m = blockIdx.x;
    const int e = threadIdx.x;
    const float x = emb[(size_t)words[m] * E_ + e];
    __nv_bfloat16 hi, lo; bf16split(x, hi, lo);
    const size_t base = (size_t)m * (3*E_) + e;
    g_Xembs[base] = hi; g_Xembs[base + E_] = hi; g_Xembs[base + 2*E_] = lo;
}

// ---------------- char LSTM gate step (sorted slots; writes split h) ----------
__global__ void char_gate(const int* __restrict__ chars,
                          const float* __restrict__ cbias, int t, int useZ)
{
    const int n = blockIdx.y;                  // slot
    if (t >= g_slen[n]) return;                // frozen slots are a suffix
    const int j = blockIdx.x * blockDim.x + threadIdx.x;   // 0..1023
    const int tok = chars[g_perm[n] * Wc_ + t];
    const float* p = g_P + (size_t)tok * CG_;
    float zi = p[j]        + cbias[j];
    float zf = p[CH_+j]    + cbias[CH_+j];
    float zg = p[2*CH_+j]  + cbias[2*CH_+j];
    float zo = p[3*CH_+j]  + cbias[3*CH_+j];
    if (useZ) {
        const float* Z = g_Zc + (size_t)n * CG_;
        zi += Z[j]; zf += Z[CH_+j]; zg += Z[2*CH_+j]; zo += Z[3*CH_+j];
    }
    float c  = g_cc[(size_t)n*CH_+j];
    float cn = sigf(zf)*c + sigf(zi)*tanhf(zg);
    float hn = sigf(zo)*tanhf(cn);
    g_cc[(size_t)n*CH_+j] = cn;
    g_ch[(size_t)n*CH_+j] = hn;
    __nv_bfloat16 hi, lo; bf16split(hn, hi, lo);
    const size_t base = (size_t)n * (3*CH_) + j;
    g_hs[base] = hi; g_hs[base + CH_] = hi; g_hs[base + 2*CH_] = lo;
}

// ---------------- final head ----------------
__global__ __launch_bounds__(256)
void final_linear(const int* __restrict__ wnum, const float* __restrict__ W,
                  const float* __restrict__ bias, float* __restrict__ out)
{
    const int row = blockIdx.x;         // 0..8191
    const int b = row >> 7;
    const int s = row & (S_ - 1);
    const bool valid = s < wnum[b];
    const int slot = g_iperm[row];
    __shared__ float v[CH_];
    __shared__ float sred[8*NC_];
    const int tid = threadIdx.x;
    for (int j = tid; j < CH_; j += 256) {
        float x = g_H1[(size_t)row*CH_ + j];
        if (valid) x += g_ch[(size_t)slot*CH_ + j];
        v[j] = x;
    }
    __syncthreads();
    float acc[NC_];
#pragma unroll
    for (int c2 = 0; c2 < NC_; ++c2) acc[c2] = 0.f;
    for (int j = tid; j < CH_; j += 256) {
        float x = v[j];
#pragma unroll
        for (int c2 = 0; c2 < NC_; ++c2)
            acc[c2] = fmaf(x, W[c2*CH_ + j], acc[c2]);
    }
#pragma unroll
    for (int c2 = 0; c2 < NC_; ++c2)
#pragma unroll
        for (int off = 16; off > 0; off >>= 1)
            acc[c2] += __shfl_down_sync(0xffffffffu, acc[c2], off);
    const int lane = tid & 31, w = tid >> 5;
    if (lane == 0)
#pragma unroll
        for (int c2 = 0; c2 < NC_; ++c2) sred[w*NC_ + c2] = acc[c2];
    __syncthreads();
    if (tid < NC_) {
        float sum = bias[tid];
#pragma unroll
        for (int w2 = 0; w2 < 8; ++w2) sum += sred[w2*NC_ + tid];
        out[(size_t)row*NC_ + tid] = sum;
    }
}

// ================================================================================
extern "C" void kernel_launch(void* const* d_in, const int* in_sizes, int n_in,
                              void* d_out, int out_size)
{
    (void)in_sizes; (void)n_in; (void)out_size;
    const int*   words     = (const int*)  d_in[0];
    const int*   words_num = (const int*)  d_in[1];
    const int*   chars     = (const int*)  d_in[2];
    const int*   char_lens = (const int*)  d_in[3];
    const float* word_emb  = (const float*)d_in[4];
    const float* char_emb  = (const float*)d_in[5];
    const float* l0_Wih    = (const float*)d_in[6];
    const float* l0_Whh    = (const float*)d_in[7];
    const float* l0_b      = (const float*)d_in[8];
    const float* l1_Wih    = (const float*)d_in[9];
    const float* l1_Whh    = (const float*)d_in[10];
    const float* l1_b      = (const float*)d_in[11];
    const float* c_Wih     = (const float*)d_in[12];
    const float* c_Whh     = (const float*)d_in[13];
    const float* c_b       = (const float*)d_in[14];
    const float* lin_W     = (const float*)d_in[15];
    const float* lin_b     = (const float*)d_in[16];
    float* out = (float*)d_out;

    float *XGf, *XGb, *H0, *H1, *hpp, *P, *Zc, *ch, *cc;
    __nv_bfloat16 *Xembs, *H0s, *hsb, *Wc2, *Wih0s, *Wih1s;
    unsigned* bar;
    int *hist, *act;
    cudaGetSymbolAddress((void**)&Xembs, g_Xembs);
    cudaGetSymbolAddress((void**)&XGf,  g_XGf);
    cudaGetSymbolAddress((void**)&XGb,  g_XGb);
    cudaGetSymbolAddress((void**)&H0,   g_H0);
    cudaGetSymbolAddress((void**)&H0s,  g_H0s);
    cudaGetSymbolAddress((void**)&H1,   g_H1);
    cudaGetSymbolAddress((void**)&hpp,  g_hpp);
    cudaGetSymbolAddress((void**)&bar,  g_bar);
    cudaGetSymbolAddress((void**)&P,    g_P);
    cudaGetSymbolAddress((void**)&Zc,   g_Zc);
    cudaGetSymbolAddress((void**)&ch,   g_ch);
    cudaGetSymbolAddress((void**)&hsb,  g_hs);
    cudaGetSymbolAddress((void**)&cc,   g_cc);
    cudaGetSymbolAddress((void**)&Wc2,  g_Wc2);
    cudaGetSymbolAddress((void**)&Wih0s,g_Wih0s);
    cudaGetSymbolAddress((void**)&Wih1s,g_Wih1s);
    cudaGetSymbolAddress((void**)&hist, g_hist);
    cudaGetSymbolAddress((void**)&act,  g_act);

    // ---- char length sort ----
    cudaMemsetAsync(hist, 0, (Wc_ + 1) * sizeof(int), 0);
    hist_k<<<NW_/256, 256>>>(char_lens);
    scan_k<<<1, 32>>>();
    scatter_k<<<NW_/256, 256>>>(char_lens);

    // ---- weight splits (bf16x3, B-side layout [hi|lo|hi]) ----
    split_k<<<(G_*E_ + 255)/256, 256>>>(l0_Wih,                     Wih0s,                     E_,  G_*E_,  0);
    split_k<<<(G_*E_ + 255)/256, 256>>>(l0_Wih + (size_t)G_*E_,     Wih0s + (size_t)G_*3*E_,   E_,  G_*E_,  0);
    split_k<<<(G_*CH_ + 255)/256, 256>>>(l1_Wih,                    Wih1s,                     CH_, G_*CH_, 0);
    split_k<<<(G_*CH_ + 255)/256, 256>>>(l1_Wih + (size_t)G_*CH_,   Wih1s + (size_t)G_*3*CH_,  CH_, G_*CH_, 0);
    split_k<<<(CG_*CH_ + 255)/256, 256>>>(c_Whh,                    Wc2,                       CH_, CG_*CH_, 0);

    // ---- word embeddings (split) ----
    embed_words<<<NW_, E_>>>(words, word_emb);

    // ---- word BiLSTM layer 0 (K'=768) ----
    {
        const float* Whh0 = l0_Whh;
        const float* Whh1 = l0_Whh + (size_t)G_ * H_;
        hgemm<<<dim3(G_/128, NW_/128), 256>>>(Xembs, Wih0s,                    XGf, NW_, G_, 3*E_, nullptr, 0);
        hgemm<<<dim3(G_/128, NW_/128), 256>>>(Xembs, Wih0s + (size_t)G_*3*E_,  XGb, NW_, G_, 3*E_, nullptr, 0);
        cudaMemsetAsync(H0,  0, (size_t)NW_*CH_*sizeof(float), 0);
        cudaMemsetAsync(H0s, 0, (size_t)NW_*3*CH_*sizeof(__nv_bfloat16), 0);
        cudaMemsetAsync(hpp, 0, (size_t)2*2*B_*H_*sizeof(float), 0);
        cudaMemsetAsync(bar, 0, sizeof(unsigned), 0);
        word_layer_persist<<<NBLK_, 256>>>(Whh0, Whh1, XGf, XGb, words_num, l0_b, H0, H0s);
    }

    // ---- word BiLSTM layer 1 (K'=3072) ----
    {
        const float* Whh0 = l1_Whh;
        const float* Whh1 = l1_Whh + (size_t)G_ * H_;
        hgemm<<<dim3(G_/128, NW_/128), 256>>>(H0s, Wih1s,                     XGf, NW_, G_, 3*CH_, nullptr, 0);
        hgemm<<<dim3(G_/128, NW_/128), 256>>>(H0s, Wih1s + (size_t)G_*3*CH_,  XGb, NW_, G_, 3*CH_, nullptr, 0);
        cudaMemsetAsync(H1,  0, (size_t)NW_*CH_*sizeof(float), 0);
        cudaMemsetAsync(hpp, 0, (size_t)2*2*B_*H_*sizeof(float), 0);
        cudaMemsetAsync(bar, 0, sizeof(unsigned), 0);
        word_layer_persist<<<NBLK_, 256>>>(Whh0, Whh1, XGf, XGb, words_num, l1_b, H1, nullptr);
    }

    // ---- char LSTM (sorted by length desc, bf16x3 tensor-core recurrence) ----
    sgemm128<<<dim3(CG_/128, 1), 256>>>(char_emb, c_Wih, P, 128, CG_, E_);
    cudaMemsetAsync(ch,  0, (size_t)NW_*CH_*sizeof(float), 0);
    cudaMemsetAsync(cc,  0, (size_t)NW_*CH_*sizeof(float), 0);
    cudaMemsetAsync(hsb, 0, (size_t)NW_*3*CH_*sizeof(__nv_bfloat16), 0);
    for (int t = 0; t < Wc_; ++t) {
        if (t > 0)
            hgemm<<<dim3(CG_/128, NW_/128), 256>>>(hsb, Wc2, Zc, NW_, CG_, 3*CH_, act, t);
        char_gate<<<dim3(CH_/256, NW_), 256>>>(chars, c_b, t, t > 0);
    }

    // ---- head ----
    final_linear<<<NW_, 256>>>(words_num, lin_W, lin_b, out);
}

// round 5
// speedup vs baseline: 2.3356x; 1.0432x over previous
#include <cuda_runtime.h>
#include <cuda_bf16.h>
#include <cstdint>
#include <cstddef>

// Problem constants
#define B_   64
#define S_   128
#define Wc_  16
#define E_   256
#define H_   512
#define NC_  20
#define NW_  (B_*S_)        // 8192 words total
#define G_   (4*H_)         // 2048 word-LSTM gate width
#define CH_  (2*H_)         // 1024 char-LSTM hidden
#define CG_  (4*CH_)        // 4096 char-LSTM gate width

#define NBLK_ 128           // persistent word-layer blocks
#define LDS_  72            // hgemm smem halfword stride (64 + 8 pad)

// ---------------- scratch (static device globals; no allocation) ----------------
__device__ __nv_bfloat16 g_Xembs[(size_t)NW_*3*E_];    // split word emb   [8192,768]
__device__ float g_XGf [(size_t)NW_*G_];               // fwd x-gates      [8192,2048]
__device__ float g_XGb [(size_t)NW_*G_];               // bwd x-gates      [8192,2048]
__device__ float g_H0  [(size_t)NW_*CH_];              // layer0 out fp32 (scratch)
__device__ __nv_bfloat16 g_H0s[(size_t)NW_*3*CH_];     // layer0 out split [8192,3072]
__device__ float g_H1  [(size_t)NW_*CH_];              // layer1 output    [8192,1024]
__device__ float g_hpp[(size_t)2*2*B_*H_];             // h ping-pong
__device__ unsigned g_bar;                             // grid barrier counter
__device__ float g_P  [(size_t)128*CG_];               // char_emb @ c_Wih.T [128,4096]
__device__ float g_Zc [(size_t)NW_*CG_];               // char recurrent gates (sorted)
__device__ float g_ch [(size_t)NW_*CH_];               // char h fp32 (sorted slots)
__device__ __nv_bfloat16 g_hs[(size_t)NW_*3*CH_];      // char h split [8192,3072]
__device__ float g_cc [(size_t)NW_*CH_];               // char c state (sorted)
__device__ __nv_bfloat16 g_Wc2   [(size_t)CG_*3*CH_];  // c_Whh split  [4096,3072]
__device__ __nv_bfloat16 g_Wih0s [(size_t)2*G_*3*E_];  // l0_Wih split [2][2048,768]
__device__ __nv_bfloat16 g_Wih1s [(size_t)2*G_*3*CH_]; // l1_Wih split [2][2048,3072]

// ---- length-sort bookkeeping ----
__device__ int g_hist[Wc_ + 1];
__device__ int g_off [Wc_ + 1];
__device__ int g_act [Wc_ + 1];
__device__ int g_perm [NW_];
__device__ int g_iperm[NW_];
__device__ int g_slen [NW_];

__device__ __forceinline__ float sigf(float x) { return 1.f / (1.f + __expf(-x)); }

__device__ __forceinline__ void bf16split(float x, __nv_bfloat16& hi, __nv_bfloat16& lo)
{
    hi = __float2bfloat16(x);
    lo = __float2bfloat16(x - __bfloat162float(hi));
}

__device__ __forceinline__ void cp16(void* dst, const void* src)
{
    uint32_t d = (uint32_t)__cvta_generic_to_shared(dst);
    asm volatile("cp.async.cg.shared.global [%0], [%1], 16;" :: "r"(d), "l"(src));
}

// ---------------- counting sort by char_lens (descending) ----------------
__global__ void hist_k(const int* __restrict__ clens)
{
    const int i = blockIdx.x * blockDim.x + threadIdx.x;
    if (i < NW_) atomicAdd(&g_hist[clens[i]], 1);
}
__global__ void scan_k()
{
    if (threadIdx.x == 0) {
        int off = 0;
        for (int len = Wc_; len >= 1; --len) { g_off[len] = off; off += g_hist[len]; }
        for (int t = 0; t <= Wc_; ++t) {
            int a = 0;
            for (int l = t + 1; l <= Wc_; ++l) a += g_hist[l];
            g_act[t] = a;
        }
    }
}
__global__ void scatter_k(const int* __restrict__ clens)
{
    const int i = blockIdx.x * blockDim.x + threadIdx.x;
    if (i < NW_) {
        const int len = clens[i];
        const int s = atomicAdd(&g_off[len], 1);
        g_perm[s] = i;
        g_iperm[i] = s;
        g_slen[s] = len;
    }
}

// ---------------- fp32 -> bf16x3 split of a weight matrix (B-side: [hi|lo|hi]) --
__global__ void split_k(const float* __restrict__ src, __nv_bfloat16* __restrict__ dst,
                        int K, int total)
{
    const int i = blockIdx.x * blockDim.x + threadIdx.x;
    if (i >= total) return;
    const int n = i / K, k = i % K;
    __nv_bfloat16 hi, lo;
    bf16split(src[i], hi, lo);
    const size_t base = (size_t)n * 3 * K;
    dst[base + k] = hi; dst[base + K + k] = lo; dst[base + 2*K + k] = hi;
}

// ---------------- bf16 tensor-core GEMM: C[M,N] = A'[M,K] @ B'[N,K]^T ----------
// bf16x3-split operands. 128x128 tile, 8 warps (2x4), warp tile 64x32,
// BK=64, 2-stage cp.async double buffer, mma.m16n8k16, fp32 accumulate.
// Requires K % 64 == 0. If act != nullptr, row tiles at/after act[step] exit.
__global__ __launch_bounds__(256)
void hgemm(const __nv_bfloat16* __restrict__ A, const __nv_bfloat16* __restrict__ Bm,
           float* __restrict__ C, int M, int N, int K,
           const int* __restrict__ act, int step)
{
    const int row0 = blockIdx.y * 128;
    if (act && row0 >= act[step]) return;
    const int col0 = blockIdx.x * 128;

    extern __shared__ __nv_bfloat16 smem_[];
    __nv_bfloat16* const sA[2] = { smem_,                smem_ + 2*128*LDS_ };
    __nv_bfloat16* const sB[2] = { smem_ + 128*LDS_,     smem_ + 3*128*LDS_ };

    const int tid  = threadIdx.x;
    const int lane = tid & 31;
    const int wid  = tid >> 5;
    const int wm   = (wid & 1) * 64;
    const int wn   = (wid >> 1) * 32;

    const int lr = tid >> 1;          // 0..127
    const int cb = (tid & 1) * 4;     // chunk base (16B chunks of the 64-col row)

    float acc[4][4][4];
#pragma unroll
    for (int mi = 0; mi < 4; ++mi)
#pragma unroll
        for (int ni = 0; ni < 4; ++ni)
#pragma unroll
            for (int f = 0; f < 4; ++f) acc[mi][ni][f] = 0.f;

    const int KT = K >> 6;

    // prologue: stage 0
    {
        const __nv_bfloat16* Ap = A  + (size_t)(row0 + lr) * K + cb * 8;
        const __nv_bfloat16* Bp = Bm + (size_t)(col0 + lr) * K + cb * 8;
#pragma unroll
        for (int c = 0; c < 4; ++c) {
            cp16(&sA[0][lr * LDS_ + (cb + c) * 8], Ap + c * 8);
            cp16(&sB[0][lr * LDS_ + (cb + c) * 8], Bp + c * 8);
        }
        asm volatile("cp.async.commit_group;");
    }

    for (int kt = 0; kt < KT; ++kt) {
        const int buf = kt & 1;
        if (kt + 1 < KT) {
            const int k0 = (kt + 1) << 6;
            const __nv_bfloat16* Ap = A  + (size_t)(row0 + lr) * K + k0 + cb * 8;
            const __nv_bfloat16* Bp = Bm + (size_t)(col0 + lr) * K + k0 + cb * 8;
#pragma unroll
            for (int c = 0; c < 4; ++c) {
                cp16(&sA[buf ^ 1][lr * LDS_ + (cb + c) * 8], Ap + c * 8);
                cp16(&sB[buf ^ 1][lr * LDS_ + (cb + c) * 8], Bp + c * 8);
            }
            asm volatile("cp.async.commit_group;");
            asm volatile("cp.async.wait_group 1;");
        } else {
            asm volatile("cp.async.wait_group 0;");
        }
        __syncthreads();

        const __nv_bfloat16* As = sA[buf];
        const __nv_bfloat16* Bs = sB[buf];
#pragma unroll
        for (int ks = 0; ks < 4; ++ks) {
            uint32_t a[4][4], b[4][2];
#pragma unroll
            for (int mi = 0; mi < 4; ++mi) {
                uint32_t addr = (uint32_t)__cvta_generic_to_shared(
                    &As[(wm + mi*16 + (lane & 15)) * LDS_ + ks*16 + (lane >> 4) * 8]);
                asm volatile("ldmatrix.sync.aligned.m8n8.x4.shared.b16 {%0,%1,%2,%3}, [%4];"
                    : "=r"(a[mi][0]), "=r"(a[mi][1]), "=r"(a[mi][2]), "=r"(a[mi][3])
                    : "r"(addr));
            }
#pragma unroll
            for (int ni = 0; ni < 4; ++ni) {
                uint32_t addr = (uint32_t)__cvta_generic_to_shared(
                    &Bs[(wn + ni*8 + (lane & 7)) * LDS_ + ks*16 + ((lane >> 3) & 1) * 8]);
                asm volatile("ldmatrix.sync.aligned.m8n8.x2.shared.b16 {%0,%1}, [%2];"
                    : "=r"(b[ni][0]), "=r"(b[ni][1]) : "r"(addr));
            }
#pragma unroll
            for (int mi = 0; mi < 4; ++mi)
#pragma unroll
                for (int ni = 0; ni < 4; ++ni) {
                    asm volatile(
                        "mma.sync.aligned.m16n8k16.row.col.f32.bf16.bf16.f32 "
                        "{%0,%1,%2,%3}, {%4,%5,%6,%7}, {%8,%9}, {%0,%1,%2,%3};"
                        : "+f"(acc[mi][ni][0]), "+f"(acc[mi][ni][1]),
                          "+f"(acc[mi][ni][2]), "+f"(acc[mi][ni][3])
                        : "r"(a[mi][0]), "r"(a[mi][1]), "r"(a[mi][2]), "r"(a[mi][3]),
                          "r"(b[ni][0]), "r"(b[ni][1]));
                }
        }
        __syncthreads();
    }

#pragma unroll
    for (int mi = 0; mi < 4; ++mi)
#pragma unroll
        for (int ni = 0; ni < 4; ++ni) {
            const int r = row0 + wm + mi*16 + (lane >> 2);
            const int c = col0 + wn + ni*8 + (lane & 3) * 2;
            float2 v0 = make_float2(acc[mi][ni][0], acc[mi][ni][1]);
            float2 v1 = make_float2(acc[mi][ni][2], acc[mi][ni][3]);
            *(float2*)&C[(size_t)r * N + c]       = v0;
            *(float2*)&C[(size_t)(r + 8) * N + c] = v1;
        }
}

// ---------------- fp32 SGEMM (only for P = char_emb @ c_Wih.T, M=128) ----------
__global__ __launch_bounds__(256)
void sgemm128(const float* __restrict__ A, const float* __restrict__ Bm,
              float* __restrict__ C, int M, int N, int K)
{
    __shared__ float As[8][128];
    __shared__ float Bs[8][128];
    const int tid = threadIdx.x;
    const int tx  = tid & 15;
    const int ty  = tid >> 4;
    const int row0 = blockIdx.y * 128;
    const int col0 = blockIdx.x * 128;
    const int lr = tid >> 1;
    const int lk = (tid & 1) * 4;

    const float* Ap = A  + (size_t)(row0 + lr) * K + lk;
    const float* Bp = Bm + (size_t)(col0 + lr) * K + lk;

    float acc[8][8];
#pragma unroll
    for (int i = 0; i < 8; ++i)
#pragma unroll
        for (int j = 0; j < 8; ++j) acc[i][j] = 0.f;

    {
        float4 a = *(const float4*)Ap;
        float4 b = *(const float4*)Bp;
        As[lk+0][lr] = a.x; As[lk+1][lr] = a.y; As[lk+2][lr] = a.z; As[lk+3][lr] = a.w;
        Bs[lk+0][lr] = b.x; Bs[lk+1][lr] = b.y; Bs[lk+2][lr] = b.z; Bs[lk+3][lr] = b.w;
    }
    __syncthreads();

    int k0 = 0;
    while (true) {
        const int kn = k0 + 8;
        const bool more = kn < K;
        float4 an, bn;
        if (more) { an = *(const float4*)(Ap + kn); bn = *(const float4*)(Bp + kn); }
#pragma unroll
        for (int k = 0; k < 8; ++k) {
            float4 a0 = *(const float4*)&As[k][ty*8];
            float4 a1 = *(const float4*)&As[k][ty*8+4];
            float4 b0 = *(const float4*)&Bs[k][tx*8];
            float4 b1 = *(const float4*)&Bs[k][tx*8+4];
            float av[8] = {a0.x,a0.y,a0.z,a0.w,a1.x,a1.y,a1.z,a1.w};
            float bv[8] = {b0.x,b0.y,b0.z,b0.w,b1.x,b1.y,b1.z,b1.w};
#pragma unroll
            for (int i = 0; i < 8; ++i)
#pragma unroll
                for (int j = 0; j < 8; ++j)
                    acc[i][j] = fmaf(av[i], bv[j], acc[i][j]);
        }
        if (!more) break;
        __syncthreads();
        As[lk+0][lr] = an.x; As[lk+1][lr] = an.y; As[lk+2][lr] = an.z; As[lk+3][lr] = an.w;
        Bs[lk+0][lr] = bn.x; Bs[lk+1][lr] = bn.y; Bs[lk+2][lr] = bn.z; Bs[lk+3][lr] = bn.w;
        __syncthreads();
        k0 = kn;
    }

#pragma unroll
    for (int i = 0; i < 8; ++i) {
        const int r = row0 + ty*8 + i;
        float4 o0, o1;
        o0.x = acc[i][0]; o0.y = acc[i][1]; o0.z = acc[i][2]; o0.w = acc[i][3];
        o1.x = acc[i][4]; o1.y = acc[i][5]; o1.z = acc[i][6]; o1.w = acc[i][7];
        *(float4*)(C + (size_t)r*N + col0 + tx*8)     = o0;
        *(float4*)(C + (size_t)r*N + col0 + tx*8 + 4) = o1;
    }
}

// ---------------- persistent word BiLSTM layer ----------------
__global__ __launch_bounds__(256)
void word_layer_persist(const float* __restrict__ Whh0, const float* __restrict__ Whh1,
                        const float* __restrict__ XGf, const float* __restrict__ XGb,
                        const int* __restrict__ lens, const float* __restrict__ bias,
                        float* __restrict__ Hout, __nv_bfloat16* __restrict__ Houts)
{
    __shared__ float hs[64][68];
    __shared__ float ws[32][68];

    const int tid = threadIdx.x;
    const int jj  = tid & 7;
    const int bb  = tid >> 3;             // 0..31
    const int dir = blockIdx.x >> 6;
    const int jt  = (blockIdx.x & 63) << 3;
    const int j   = jt + jj;

    const float* W  = dir ? Whh1 : Whh0;
    const float* XG = dir ? XGb : XGf;
    const float* bv = bias + (size_t)dir * G_;
    float bg[4];
#pragma unroll
    for (int g = 0; g < 4; ++g) bg[g] = bv[g * H_ + j];

    const int len0 = lens[bb];
    const int len1 = lens[bb + 32];

    float hreg0 = 0.f, creg0 = 0.f;
    float hreg1 = 0.f, creg1 = 0.f;

    for (int t = 0; t < S_; ++t) {
        const float* hcur = g_hpp + (size_t)(((t    ) & 1) * 2 + dir) * (B_*H_);
        float*       hnxt = g_hpp + (size_t)(((t + 1) & 1) * 2 + dir) * (B_*H_);

        float acc[2][4];
#pragma unroll
        for (int b2 = 0; b2 < 2; ++b2)
#pragma unroll
            for (int g = 0; g < 4; ++g) acc[b2][g] = 0.f;

        for (int k0 = 0; k0 < H_; k0 += 64) {
#pragma unroll
            for (int i = 0; i < 4; ++i) {
                const int idx = tid + i * 256;
                const int r = idx >> 4, c = idx & 15;
                float4 v = __ldcg((const float4*)(hcur + (size_t)r * H_ + k0 + c * 4));
                *(float4*)&hs[r][c * 4] = v;
            }
#pragma unroll
            for (int i = 0; i < 2; ++i) {
                const int idx = tid + i * 256;
                const int w = idx >> 4, c = idx & 15;
                const int g = w >> 3, jl = w & 7;
                float4 v = *(const float4*)(W + (size_t)(g * H_ + jt + jl) * H_ + k0 + c * 4);
                *(float4*)&ws[w][c * 4] = v;
            }
            __syncthreads();
#pragma unroll
            for (int k4 = 0; k4 < 16; ++k4) {
                float4 a0 = *(const float4*)&hs[bb][k4 * 4];
                float4 a1 = *(const float4*)&hs[bb + 32][k4 * 4];
#pragma unroll
                for (int g = 0; g < 4; ++g) {
                    float4 w4 = *(const float4*)&ws[g * 8 + jj][k4 * 4];
                    acc[0][g] = fmaf(a0.x, w4.x, acc[0][g]);
                    acc[0][g] = fmaf(a0.y, w4.y, acc[0][g]);
                    acc[0][g] = fmaf(a0.z, w4.z, acc[0][g]);
                    acc[0][g] = fmaf(a0.w, w4.w, acc[0][g]);
                    acc[1][g] = fmaf(a1.x, w4.x, acc[1][g]);
                    acc[1][g] = fmaf(a1.y, w4.y, acc[1][g]);
                    acc[1][g] = fmaf(a1.z, w4.z, acc[1][g]);
                    acc[1][g] = fmaf(a1.w, w4.w, acc[1][g]);
                }
            }
            __syncthreads();
        }

#pragma unroll
        for (int b2 = 0; b2 < 2; ++b2) {
            const int b = bb + b2 * 32;
            const int len = b2 ? len1 : len0;
            const bool valid = t < len;
            const int src = (dir == 0) ? t : (valid ? (len - 1 - t) : t);
            const float* xg = XG + (size_t)(b * S_ + src) * G_ + jt + jj;
            float zi = acc[b2][0] + xg[0]      + bg[0];
            float zf = acc[b2][1] + xg[H_]     + bg[1];
            float zg = acc[b2][2] + xg[2*H_]   + bg[2];
            float zo = acc[b2][3] + xg[3*H_]   + bg[3];
            float c_old = b2 ? creg1 : creg0;
            float cn = sigf(zf) * c_old + sigf(zi) * tanhf(zg);
            float hn = sigf(zo) * tanhf(cn);
            float h_old = b2 ? hreg1 : hreg0;
            float h_out = valid ? hn : h_old;
            float c_out = valid ? cn : c_old;
            if (b2) { hreg1 = h_out; creg1 = c_out; }
            else    { hreg0 = h_out; creg0 = c_out; }
            __stcg(hnxt + (size_t)b * H_ + j, h_out);
            if (dir == 0) {
                const float v = valid ? hn : 0.f;
                Hout[(size_t)(b * S_ + t) * CH_ + j] = v;
                if (Houts) {
                    __nv_bfloat16 hi, lo; bf16split(v, hi, lo);
                    const size_t base = (size_t)(b * S_ + t) * (3*CH_) + j;
                    Houts[base] = hi; Houts[base + CH_] = hi; Houts[base + 2*CH_] = lo;
                }
            } else if (valid) {
                Hout[(size_t)(b * S_ + src) * CH_ + H_ + j] = hn;
                if (Houts) {
                    __nv_bfloat16 hi, lo; bf16split(hn, hi, lo);
                    const size_t base = (size_t)(b * S_ + src) * (3*CH_) + H_ + j;
                    Houts[base] = hi; Houts[base + CH_] = hi; Houts[base + 2*CH_] = lo;
                }
            }
        }

        if (t < S_ - 1) {
            __syncthreads();
            if (tid == 0) {
                __threadfence();
                atomicAdd(&g_bar, 1u);
                const unsigned tgt = (unsigned)(t + 1) * (unsigned)NBLK_;
                volatile unsigned* p = &g_bar;
                while (*p < tgt) __nanosleep(64);
            }
            __syncthreads();
        }
    }
}

// ---------------- word embedding gather (writes split directly) ----------------
__global__ void embed_words(const int* __restrict__ words, const float* __restrict__ emb)
{
    const int m = blockIdx.x;
    const int e = threadIdx.x;
    const float x = emb[(size_t)words[m] * E_ + e];
    __nv_bfloat16 hi, lo; bf16split(x, hi, lo);
    const size_t base = (size_t)m * (3*E_) + e;
    g_Xembs[base] = hi; g_Xembs[base + E_] = hi; g_Xembs[base + 2*E_] = lo;
}

// ---------------- char LSTM gate step (sorted slots; writes split h) ----------
__global__ void char_gate(const int* __restrict__ chars,
                          const float* __restrict__ cbias, int t, int useZ)
{
    const int n = blockIdx.y;                  // slot
    if (t >= g_slen[n]) return;                // frozen slots are a suffix
    const int j = blockIdx.x * blockDim.x + threadIdx.x;   // 0..1023
    const int tok = chars[g_perm[n] * Wc_ + t];
    const float* p = g_P + (size_t)tok * CG_;
    float zi = p[j]        + cbias[j];
    float zf = p[CH_+j]    + cbias[CH_+j];
    float zg = p[2*CH_+j]  + cbias[2*CH_+j];
    float zo = p[3*CH_+j]  + cbias[3*CH_+j];
    if (useZ) {
        const float* Z = g_Zc + (size_t)n * CG_;
        zi += Z[j]; zf += Z[CH_+j]; zg += Z[2*CH_+j]; zo += Z[3*CH_+j];
    }
    float c  = g_cc[(size_t)n*CH_+j];
    float cn = sigf(zf)*c + sigf(zi)*tanhf(zg);
    float hn = sigf(zo)*tanhf(cn);
    g_cc[(size_t)n*CH_+j] = cn;
    g_ch[(size_t)n*CH_+j] = hn;
    __nv_bfloat16 hi, lo; bf16split(hn, hi, lo);
    const size_t base = (size_t)n * (3*CH_) + j;
    g_hs[base] = hi; g_hs[base + CH_] = hi; g_hs[base + 2*CH_] = lo;
}

// ---------------- final head ----------------
__global__ __launch_bounds__(256)
void final_linear(const int* __restrict__ wnum, const float* __restrict__ W,
                  const float* __restrict__ bias, float* __restrict__ out)
{
    const int row = blockIdx.x;         // 0..8191
    const int b = row >> 7;
    const int s = row & (S_ - 1);
    const bool valid = s < wnum[b];
    const int slot = g_iperm[row];
    __shared__ float v[CH_];
    __shared__ float sred[8*NC_];
    const int tid = threadIdx.x;
    for (int j = tid; j < CH_; j += 256) {
        float x = g_H1[(size_t)row*CH_ + j];
        if (valid) x += g_ch[(size_t)slot*CH_ + j];
        v[j] = x;
    }
    __syncthreads();
    float acc[NC_];
#pragma unroll
    for (int c2 = 0; c2 < NC_; ++c2) acc[c2] = 0.f;
    for (int j = tid; j < CH_; j += 256) {
        float x = v[j];
#pragma unroll
        for (int c2 = 0; c2 < NC_; ++c2)
            acc[c2] = fmaf(x, W[c2*CH_ + j], acc[c2]);
    }
#pragma unroll
    for (int c2 = 0; c2 < NC_; ++c2)
#pragma unroll
        for (int off = 16; off > 0; off >>= 1)
            acc[c2] += __shfl_down_sync(0xffffffffu, acc[c2], off);
    const int lane = tid & 31, w = tid >> 5;
    if (lane == 0)
#pragma unroll
        for (int c2 = 0; c2 < NC_; ++c2) sred[w*NC_ + c2] = acc[c2];
    __syncthreads();
    if (tid < NC_) {
        float sum = bias[tid];
#pragma unroll
        for (int w2 = 0; w2 < 8; ++w2) sum += sred[w2*NC_ + tid];
        out[(size_t)row*NC_ + tid] = sum;
    }
}

// ================================================================================
extern "C" void kernel_launch(void* const* d_in, const int* in_sizes, int n_in,
                              void* d_out, int out_size)
{
    (void)in_sizes; (void)n_in; (void)out_size;
    const int*   words     = (const int*)  d_in[0];
    const int*   words_num = (const int*)  d_in[1];
    const int*   chars     = (const int*)  d_in[2];
    const int*   char_lens = (const int*)  d_in[3];
    const float* word_emb  = (const float*)d_in[4];
    const float* char_emb  = (const float*)d_in[5];
    const float* l0_Wih    = (const float*)d_in[6];
    const float* l0_Whh    = (const float*)d_in[7];
    const float* l0_b      = (const float*)d_in[8];
    const float* l1_Wih    = (const float*)d_in[9];
    const float* l1_Whh    = (const float*)d_in[10];
    const float* l1_b      = (const float*)d_in[11];
    const float* c_Wih     = (const float*)d_in[12];
    const float* c_Whh     = (const float*)d_in[13];
    const float* c_b       = (const float*)d_in[14];
    const float* lin_W     = (const float*)d_in[15];
    const float* lin_b     = (const float*)d_in[16];
    float* out = (float*)d_out;

    float *XGf, *XGb, *H0, *H1, *hpp, *P, *Zc, *ch, *cc;
    __nv_bfloat16 *Xembs, *H0s, *hsb, *Wc2, *Wih0s, *Wih1s;
    unsigned* bar;
    int *hist, *act;
    cudaGetSymbolAddress((void**)&Xembs, g_Xembs);
    cudaGetSymbolAddress((void**)&XGf,  g_XGf);
    cudaGetSymbolAddress((void**)&XGb,  g_XGb);
    cudaGetSymbolAddress((void**)&H0,   g_H0);
    cudaGetSymbolAddress((void**)&H0s,  g_H0s);
    cudaGetSymbolAddress((void**)&H1,   g_H1);
    cudaGetSymbolAddress((void**)&hpp,  g_hpp);
    cudaGetSymbolAddress((void**)&bar,  g_bar);
    cudaGetSymbolAddress((void**)&P,    g_P);
    cudaGetSymbolAddress((void**)&Zc,   g_Zc);
    cudaGetSymbolAddress((void**)&ch,   g_ch);
    cudaGetSymbolAddress((void**)&hsb,  g_hs);
    cudaGetSymbolAddress((void**)&cc,   g_cc);
    cudaGetSymbolAddress((void**)&Wc2,  g_Wc2);
    cudaGetSymbolAddress((void**)&Wih0s,g_Wih0s);
    cudaGetSymbolAddress((void**)&Wih1s,g_Wih1s);
    cudaGetSymbolAddress((void**)&hist, g_hist);
    cudaGetSymbolAddress((void**)&act,  g_act);

    const size_t HS = (size_t)4 * 128 * LDS_ * sizeof(__nv_bfloat16);   // 73728 B
    cudaFuncSetAttribute(hgemm, cudaFuncAttributeMaxDynamicSharedMemorySize, (int)HS);

    // ---- char length sort ----
    cudaMemsetAsync(hist, 0, (Wc_ + 1) * sizeof(int), 0);
    hist_k<<<NW_/256, 256>>>(char_lens);
    scan_k<<<1, 32>>>();
    scatter_k<<<NW_/256, 256>>>(char_lens);

    // ---- weight splits (bf16x3, B-side layout [hi|lo|hi]) ----
    split_k<<<(G_*E_ + 255)/256, 256>>>(l0_Wih,                     Wih0s,                     E_,  G_*E_);
    split_k<<<(G_*E_ + 255)/256, 256>>>(l0_Wih + (size_t)G_*E_,     Wih0s + (size_t)G_*3*E_,   E_,  G_*E_);
    split_k<<<(G_*CH_ + 255)/256, 256>>>(l1_Wih,                    Wih1s,                     CH_, G_*CH_);
    split_k<<<(G_*CH_ + 255)/256, 256>>>(l1_Wih + (size_t)G_*CH_,   Wih1s + (size_t)G_*3*CH_,  CH_, G_*CH_);
    split_k<<<(CG_*CH_ + 255)/256, 256>>>(c_Whh,                    Wc2,                       CH_, CG_*CH_);

    // ---- word embeddings (split) ----
    embed_words<<<NW_, E_>>>(words, word_emb);

    // ---- word BiLSTM layer 0 (K'=768) ----
    {
        const float* Whh0 = l0_Whh;
        const float* Whh1 = l0_Whh + (size_t)G_ * H_;
        hgemm<<<dim3(G_/128, NW_/128), 256, HS>>>(Xembs, Wih0s,                    XGf, NW_, G_, 3*E_, nullptr, 0);
        hgemm<<<dim3(G_/128, NW_/128), 256, HS>>>(Xembs, Wih0s + (size_t)G_*3*E_,  XGb, NW_, G_, 3*E_, nullptr, 0);
        cudaMemsetAsync(H0,  0, (size_t)NW_*CH_*sizeof(float), 0);
        cudaMemsetAsync(H0s, 0, (size_t)NW_*3*CH_*sizeof(__nv_bfloat16), 0);
        cudaMemsetAsync(hpp, 0, (size_t)2*2*B_*H_*sizeof(float), 0);
        cudaMemsetAsync(bar, 0, sizeof(unsigned), 0);
        word_layer_persist<<<NBLK_, 256>>>(Whh0, Whh1, XGf, XGb, words_num, l0_b, H0, H0s);
    }

    // ---- word BiLSTM layer 1 (K'=3072) ----
    {
        const float* Whh0 = l1_Whh;
        const float* Whh1 = l1_Whh + (size_t)G_ * H_;
        hgemm<<<dim3(G_/128, NW_/128), 256, HS>>>(H0s, Wih1s,                     XGf, NW_, G_, 3*CH_, nullptr, 0);
        hgemm<<<dim3(G_/128, NW_/128), 256, HS>>>(H0s, Wih1s + (size_t)G_*3*CH_,  XGb, NW_, G_, 3*CH_, nullptr, 0);
        cudaMemsetAsync(H1,  0, (size_t)NW_*CH_*sizeof(float), 0);
        cudaMemsetAsync(hpp, 0, (size_t)2*2*B_*H_*sizeof(float), 0);
        cudaMemsetAsync(bar, 0, sizeof(unsigned), 0);
        word_layer_persist<<<NBLK_, 256>>>(Whh0, Whh1, XGf, XGb, words_num, l1_b, H1, nullptr);
    }

    // ---- char LSTM (sorted by length desc, bf16x3 tensor-core recurrence) ----
    sgemm128<<<dim3(CG_/128, 1), 256>>>(char_emb, c_Wih, P, 128, CG_, E_);
    cudaMemsetAsync(ch,  0, (size_t)NW_*CH_*sizeof(float), 0);
    cudaMemsetAsync(cc,  0, (size_t)NW_*CH_*sizeof(float), 0);
    cudaMemsetAsync(hsb, 0, (size_t)NW_*3*CH_*sizeof(__nv_bfloat16), 0);
    for (int t = 0; t < Wc_; ++t) {
        if (t > 0)
            hgemm<<<dim3(CG_/128, NW_/128), 256, HS>>>(hsb, Wc2, Zc, NW_, CG_, 3*CH_, act, t);
        char_gate<<<dim3(CH_/256, NW_), 256>>>(chars, c_b, t, t > 0);
    }

    // ---- head ----
    final_linear<<<NW_, 256>>>(words_num, lin_W, lin_b, out);
}